// round 11
// baseline (speedup 1.0000x reference)
#include <cuda_runtime.h>
#include <cuda_bf16.h>
#include <math.h>
#include <stdint.h>

#define Nn 4096
#define Ff 512
#define Dd 64
#define Hh 8
#define HD 512   // Hh*Dd
#define Cc 40
#define C2 64    // padded class dim
#define MAXDEG 128
#define NB 256   // grid size (all co-resident: >=2 blocks/SM guaranteed)

// ---------------- scratch (static device globals; no allocation) -------------
__device__ int   g_deg[Nn];
__device__ int   g_nbr[Nn * MAXDEG];
__device__ float g_h[(size_t)Nn * HD];
__device__ float g_si[Hh * Nn];
__device__ float g_sj[Hh * Nn];
__device__ float g_x2[(size_t)Nn * HD];
__device__ float g_h2p[(size_t)Nn * C2];   // padded h2 (cols 40..63 are 0)
__device__ float g_s2i[Nn];
__device__ float g_s2j[Nn];
__device__ int   g_bar_cnt;                // zero-init; self-resetting
__device__ int   g_bar_gen;                // monotonic across replays

// ---------------- grid-wide barrier (all NB blocks co-resident) --------------
__device__ __forceinline__ void grid_sync() {
    __syncthreads();
    if (threadIdx.x == 0) {
        __threadfence();
        int gen = *(volatile int*)&g_bar_gen;
        if (atomicAdd(&g_bar_cnt, 1) == NB - 1) {
            g_bar_cnt = 0;
            __threadfence();
            *(volatile int*)&g_bar_gen = gen + 1;
        } else {
            while (*(volatile int*)&g_bar_gen == gen) __nanosleep(80);
        }
        __threadfence();
    }
    __syncthreads();
}

// ---------------- helpers ----------------------------------------------------
__device__ __forceinline__ uint32_t f2tf(float x) {
    uint32_t r;
    asm("cvt.rna.tf32.f32 %0, %1;" : "=r"(r) : "f"(x));
    return r;
}
__device__ __forceinline__ uint4 ldg_stream(const uint4* p) { return __ldcs(p); }
__device__ __forceinline__ void cp16(uint32_t dst_smem, const void* src) {
    asm volatile("cp.async.cg.shared.global [%0], [%1], 16;\n"
                 :: "r"(dst_smem), "l"(src) : "memory");
}
__device__ __forceinline__ void cp_commit() {
    asm volatile("cp.async.commit_group;\n" ::: "memory");
}
__device__ __forceinline__ void cp_wait1() {
    asm volatile("cp.async.wait_group 1;\n" ::: "memory");
}
__device__ __forceinline__ void cp_wait0() {
    asm volatile("cp.async.wait_group 0;\n" ::: "memory");
}
__device__ __forceinline__ void mma_tf32(float* c, uint32_t a0, uint32_t a1,
                                         uint32_t a2, uint32_t a3,
                                         uint32_t b0, uint32_t b1) {
    asm volatile(
        "mma.sync.aligned.m16n8k8.row.col.f32.tf32.tf32.f32 "
        "{%0,%1,%2,%3}, {%4,%5,%6,%7}, {%8,%9}, {%0,%1,%2,%3};"
        : "+f"(c[0]), "+f"(c[1]), "+f"(c[2]), "+f"(c[3])
        : "r"(a0), "r"(a1), "r"(a2), "r"(a3), "r"(b0), "r"(b1));
}

__device__ __forceinline__ int detect_mode(const unsigned char* adj) {
    if (adj[(size_t)Nn + 1] == 1) return 0;                               // u8
    if (((const uint16_t*)adj)[(size_t)Nn + 1] == 0x3F80u) return 3;      // bf16
    uint32_t v32 = ((const uint32_t*)adj)[(size_t)Nn + 1];
    if (v32 == 0x3F800000u) return 2;                                     // f32
    if (((const uint64_t*)adj)[(size_t)Nn + 1] == 0x3FF0000000000000ull) return 4; // f64
    return 1;                                                             // i32
}
__device__ __forceinline__ unsigned nz4(unsigned w) {
    unsigned c = 0;
    if (w & 0x000000FFu) c |= 1u;
    if (w & 0x0000FF00u) c |= 2u;
    if (w & 0x00FF0000u) c |= 4u;
    if (w & 0xFF000000u) c |= 8u;
    return c;
}
__device__ __forceinline__ int emit_mask(int row, int cnt, unsigned msk,
                                         int j0, int lane) {
    const unsigned FULL = 0xffffffffu;
    int c = __popc(msk);
    int pref = c;
    #pragma unroll
    for (int o = 1; o < 32; o <<= 1) {
        int n = __shfl_up_sync(FULL, pref, o);
        if (lane >= o) pref += n;
    }
    int pos = cnt + pref - c;
    while (msk) {
        int b = __ffs(msk) - 1;
        msk &= msk - 1;
        if (pos < MAXDEG) g_nbr[row * MAXDEG + pos] = j0 + b;
        pos++;
    }
    return cnt + __shfl_sync(FULL, pref, 31);
}

// one adjacency row per warp (order-preserving compaction)
__device__ void build_one_row(const unsigned char* adj, int row, int lane, int mode) {
    int cnt = 0;
    if (mode == 0) {
        const uint4* r = (const uint4*)(adj + (size_t)row * Nn);
        #pragma unroll
        for (int it = 0; it < Nn / 512; it++) {
            uint4 v = ldg_stream(&r[it * 32 + lane]);
            unsigned msk = nz4(v.x) | (nz4(v.y) << 4) | (nz4(v.z) << 8) | (nz4(v.w) << 12);
            cnt = emit_mask(row, cnt, msk, it * 512 + lane * 16, lane);
        }
    } else if (mode == 1 || mode == 2) {
        const uint4* r = (const uint4*)adj + (size_t)row * (Nn / 4);
        for (int it = 0; it < Nn / 128; it++) {
            uint4 v = ldg_stream(&r[it * 32 + lane]);
            unsigned msk = (v.x ? 1u : 0u) | (v.y ? 2u : 0u) | (v.z ? 4u : 0u) | (v.w ? 8u : 0u);
            cnt = emit_mask(row, cnt, msk, it * 128 + lane * 4, lane);
        }
    } else if (mode == 3) {
        const uint4* r = (const uint4*)adj + (size_t)row * (Nn / 8);
        for (int it = 0; it < Nn / 256; it++) {
            uint4 v = ldg_stream(&r[it * 32 + lane]);
            unsigned msk = 0;
            unsigned w[4] = {v.x, v.y, v.z, v.w};
            #pragma unroll
            for (int q = 0; q < 4; q++) {
                if (w[q] & 0x0000FFFFu) msk |= 1u << (2 * q);
                if (w[q] & 0xFFFF0000u) msk |= 2u << (2 * q);
            }
            cnt = emit_mask(row, cnt, msk, it * 256 + lane * 8, lane);
        }
    } else {
        const double* rd = (const double*)adj + (size_t)row * Nn;
        const unsigned FULL = 0xffffffffu;
        for (int base = 0; base < Nn; base += 32) {
            int j = base + lane;
            bool edge = rd[j] != 0.0;
            unsigned m = __ballot_sync(FULL, edge);
            if (edge) {
                int pos = cnt + __popc(m & ((1u << lane) - 1u));
                if (pos < MAXDEG) g_nbr[row * MAXDEG + pos] = j;
            }
            cnt += __popc(m);
        }
    }
    if (lane == 0) g_deg[row] = (cnt < MAXDEG) ? cnt : MAXDEG;
}

// --- TF32 GEMM tile (proven shapes only: 4(M) x 2(N) warps) ------------------
template <int BM, int BCH, int AVALID>
__device__ __forceinline__ void gemm_tile(
    const float* __restrict__ A, const float* __restrict__ Bp,
    float* __restrict__ Cm, int Nc, int row0, int col0,
    const float* __restrict__ avs, const float* __restrict__ avd,
    float* __restrict__ si_out, float* __restrict__ sj_out, float* sm)
{
    constexpr int K = 512;
    constexpr int WM = BM / 4;
    constexpr int MF = WM / 16;
    constexpr int NF = 4;
    constexpr int BROW = BCH * 4;

    float* As_  = sm;                       // [2][BM][36]
    float* Bs_  = sm + 2 * BM * 36;         // [2][32][72]
    float* s_si = Bs_ + 2 * 32 * 72;        // [2][BM]
    float* s_sj = s_si + 2 * BM;            // [2][BM]
    uint32_t smb = (uint32_t)__cvta_generic_to_shared(sm);
    uint32_t asb = smb;
    uint32_t bsb = smb + 2 * BM * 36 * 4;

    int t = threadIdx.x, lane = t & 31, wid = t >> 5;
    int warpM = wid & 3, warpN = wid >> 2;
    int gId = lane >> 2, tig = lane & 3;

    if (BCH < 16 && t < 64) {
        float* rp = Bs_ + t * 72;
        #pragma unroll
        for (int c = BROW; c < 72; c++) rp[c] = 0.f;
    }

    float acc[MF][NF][4];
    #pragma unroll
    for (int i = 0; i < MF; i++)
        #pragma unroll
        for (int j = 0; j < NF; j++)
            #pragma unroll
            for (int q = 0; q < 4; q++) acc[i][j][q] = 0.f;

    auto issue = [&](int stage, int k0) {
        #pragma unroll
        for (int it = 0; it < BM * 8 / 256; it++) {
            int id = t + it * 256;
            int r = id >> 3, c = id & 7;
            cp16(asb + ((stage * BM + r) * 36 + c * 4) * 4,
                 A + (size_t)(row0 + r) * K + k0 + c * 4);
        }
        constexpr int TOT = 32 * BCH;
        #pragma unroll
        for (int it = 0; it < (TOT + 255) / 256; it++) {
            int id = t + it * 256;
            if (id < TOT) {
                int r = id / BCH, c = id % BCH;
                cp16(bsb + ((stage * 32 + r) * 72 + c * 4) * 4,
                     Bp + (size_t)(k0 + r) * BROW + c * 4);
            }
        }
        cp_commit();
    };

    issue(0, 0);
    for (int kt = 0; kt < K / 32; kt++) {
        int cur = kt & 1;
        if (kt + 1 < K / 32) { issue(cur ^ 1, (kt + 1) * 32); cp_wait1(); }
        else cp_wait0();
        __syncthreads();

        const float* Asc = As_ + cur * BM * 36;
        const float* Bsc = Bs_ + cur * 32 * 72;
        #pragma unroll
        for (int ks = 0; ks < 4; ks++) {
            int kk = ks * 8;
            uint32_t ah[MF][4], al[MF][4];
            #pragma unroll
            for (int mf = 0; mf < MF; mf++) {
                int m0 = warpM * WM + mf * 16 + gId;
                float f0 = Asc[m0 * 36 + kk + tig];
                float f1 = Asc[(m0 + 8) * 36 + kk + tig];
                float f2 = Asc[m0 * 36 + kk + tig + 4];
                float f3 = Asc[(m0 + 8) * 36 + kk + tig + 4];
                ah[mf][0] = f2tf(f0); al[mf][0] = f2tf(f0 - __uint_as_float(ah[mf][0]));
                ah[mf][1] = f2tf(f1); al[mf][1] = f2tf(f1 - __uint_as_float(ah[mf][1]));
                ah[mf][2] = f2tf(f2); al[mf][2] = f2tf(f2 - __uint_as_float(ah[mf][2]));
                ah[mf][3] = f2tf(f3); al[mf][3] = f2tf(f3 - __uint_as_float(ah[mf][3]));
            }
            uint32_t bh[NF][2], bl[NF][2];
            #pragma unroll
            for (int nf = 0; nf < NF; nf++) {
                int n0 = warpN * 32 + nf * 8 + gId;
                float g0 = Bsc[(kk + tig) * 72 + n0];
                float g1 = Bsc[(kk + tig + 4) * 72 + n0];
                bh[nf][0] = f2tf(g0); bl[nf][0] = f2tf(g0 - __uint_as_float(bh[nf][0]));
                bh[nf][1] = f2tf(g1); bl[nf][1] = f2tf(g1 - __uint_as_float(bh[nf][1]));
            }
            #pragma unroll
            for (int mf = 0; mf < MF; mf++)
                #pragma unroll
                for (int nf = 0; nf < NF; nf++) {
                    mma_tf32(acc[mf][nf], ah[mf][0], ah[mf][1], ah[mf][2], ah[mf][3],
                             bl[nf][0], bl[nf][1]);
                    mma_tf32(acc[mf][nf], al[mf][0], al[mf][1], al[mf][2], al[mf][3],
                             bh[nf][0], bh[nf][1]);
                    mma_tf32(acc[mf][nf], ah[mf][0], ah[mf][1], ah[mf][2], ah[mf][3],
                             bh[nf][0], bh[nf][1]);
                }
        }
        __syncthreads();
    }

    // ---- C store ----
    #pragma unroll
    for (int mf = 0; mf < MF; mf++) {
        int r0 = row0 + warpM * WM + mf * 16 + gId;
        #pragma unroll
        for (int nf = 0; nf < NF; nf++) {
            int c0 = col0 + warpN * 32 + nf * 8 + tig * 2;
            *(float2*)&Cm[(size_t)r0 * Nc + c0] = make_float2(acc[mf][nf][0], acc[mf][nf][1]);
            *(float2*)&Cm[(size_t)(r0 + 8) * Nc + c0] = make_float2(acc[mf][nf][2], acc[mf][nf][3]);
        }
    }

    // ---- fused row dots: si/sj ----
    const unsigned FULL = 0xffffffffu;
    float advals[NF][2], asvals[NF][2];
    #pragma unroll
    for (int nf = 0; nf < NF; nf++) {
        int c = warpN * 32 + nf * 8 + tig * 2;
        advals[nf][0] = (c < AVALID) ? avd[c] : 0.f;
        asvals[nf][0] = (c < AVALID) ? avs[c] : 0.f;
        advals[nf][1] = (c + 1 < AVALID) ? avd[c + 1] : 0.f;
        asvals[nf][1] = (c + 1 < AVALID) ? avs[c + 1] : 0.f;
    }
    #pragma unroll
    for (int mf = 0; mf < MF; mf++) {
        float rAi = 0.f, rAj = 0.f, rBi = 0.f, rBj = 0.f;
        #pragma unroll
        for (int nf = 0; nf < NF; nf++) {
            rAi += acc[mf][nf][0] * advals[nf][0] + acc[mf][nf][1] * advals[nf][1];
            rAj += acc[mf][nf][0] * asvals[nf][0] + acc[mf][nf][1] * asvals[nf][1];
            rBi += acc[mf][nf][2] * advals[nf][0] + acc[mf][nf][3] * advals[nf][1];
            rBj += acc[mf][nf][2] * asvals[nf][0] + acc[mf][nf][3] * asvals[nf][1];
        }
        #pragma unroll
        for (int o = 1; o <= 2; o <<= 1) {
            rAi += __shfl_xor_sync(FULL, rAi, o);
            rAj += __shfl_xor_sync(FULL, rAj, o);
            rBi += __shfl_xor_sync(FULL, rBi, o);
            rBj += __shfl_xor_sync(FULL, rBj, o);
        }
        if (tig == 0) {
            int r = warpM * WM + mf * 16 + gId;
            s_si[warpN * BM + r] = rAi;
            s_sj[warpN * BM + r] = rAj;
            s_si[warpN * BM + r + 8] = rBi;
            s_sj[warpN * BM + r + 8] = rBj;
        }
    }
    __syncthreads();
    if (t < BM) {
        si_out[row0 + t] = s_si[t] + s_si[BM + t];
        sj_out[row0 + t] = s_sj[t] + s_sj[BM + t];
    }
}

// ================= THE single persistent kernel ==============================
__global__ __launch_bounds__(256, 2) void k_mega(
    const float* __restrict__ x, const unsigned char* __restrict__ adj,
    const float* __restrict__ W1,
    const float* __restrict__ a1_src, const float* __restrict__ a1_dst,
    const float* __restrict__ W2,
    const float* __restrict__ a2_src, const float* __restrict__ a2_dst,
    float* __restrict__ out)
{
    extern __shared__ float sm[];
    const unsigned FULL = 0xffffffffu;
    int b = blockIdx.x;
    int t = threadIdx.x, lane = t & 31, w = t >> 5;

    // ---- phase 0: adjacency build (16 rows per block, 2 per warp) ----
    {
        int mode = detect_mode(adj);
        build_one_row(adj, b * 16 + w, lane, mode);
        build_one_row(adj, b * 16 + 8 + w, lane, mode);
    }
    grid_sync();

    // ---- phase 1: GEMM1 (BM=128, proven shape; tile = this block) ----
    {
        int head = b & 7, rb = b >> 3;
        gemm_tile<128, 16, 64>(x, W1 + (size_t)head * Ff * Dd, g_h, HD,
                               rb * 128, head * 64,
                               a1_src + head * Dd, a1_dst + head * Dd,
                               g_si + head * Nn, g_sj + head * Nn, sm);
    }
    grid_sync();

    // ---- phase 2: layer-1 sparse attention + aggregate + ELU (16 nodes) ----
    {
        int*   nbr_sh = (int*)sm;           // [128]
        float* w_sh   = sm + 128;           // [8][128]
        for (int nq = 0; nq < 16; nq++) {
            int i = b * 16 + nq;
            int deg = g_deg[i];
            for (int jj = t; jj < deg; jj += 256) nbr_sh[jj] = g_nbr[i * MAXDEG + jj];
            __syncthreads();
            {
                int h = w;
                float sii = g_si[h * Nn + i];
                float ev[4];
                float m = -1e30f;
                #pragma unroll
                for (int it = 0; it < 4; it++) {
                    int jj = it * 32 + lane;
                    float e = -1e30f;
                    if (jj < deg) {
                        float xx = sii + g_sj[h * Nn + nbr_sh[jj]];
                        e = (xx >= 0.f) ? xx : 0.2f * xx;
                    }
                    ev[it] = e;
                    m = fmaxf(m, e);
                }
                #pragma unroll
                for (int o = 16; o; o >>= 1) m = fmaxf(m, __shfl_xor_sync(FULL, m, o));
                float s = 0.f;
                #pragma unroll
                for (int it = 0; it < 4; it++) {
                    int jj = it * 32 + lane;
                    float wv = (jj < deg) ? __expf(ev[it] - m) : 0.f;
                    ev[it] = wv;
                    s += wv;
                }
                #pragma unroll
                for (int o = 16; o; o >>= 1) s += __shfl_xor_sync(FULL, s, o);
                float inv = 1.f / s;
                #pragma unroll
                for (int it = 0; it < 4; it++) {
                    int jj = it * 32 + lane;
                    if (jj < deg) w_sh[h * 128 + jj] = ev[it] * inv;
                }
            }
            __syncthreads();
            {
                int h = t >> 5;
                float2 acc = make_float2(0.f, 0.f);
                const float* wrow = w_sh + h * 128;
                #pragma unroll 4
                for (int jj = 0; jj < deg; jj++) {
                    float wv = wrow[jj];
                    float2 v = *(const float2*)&g_h[(size_t)nbr_sh[jj] * HD + 2 * t];
                    acc.x += wv * v.x;
                    acc.y += wv * v.y;
                }
                float2 r;
                r.x = (acc.x > 0.f) ? acc.x : expm1f(acc.x);
                r.y = (acc.y > 0.f) ? acc.y : expm1f(acc.y);
                *(float2*)&g_x2[(size_t)i * HD + 2 * t] = r;
            }
            __syncthreads();
        }
    }
    grid_sync();

    // ---- phase 3: GEMM2 (BM=64, proven shape; blocks 0..63) ----
    if (b < 64) {
        gemm_tile<64, 10, Cc>(g_x2, W2, g_h2p, C2, b * 64, 0,
                              a2_src, a2_dst, g_s2i, g_s2j, sm);
    }
    grid_sync();

    // ---- phase 4: layer-2 sparse attention -> out (16 nodes, 2 per warp) ----
    for (int q = 0; q < 2; q++) {
        int i = b * 16 + w * 2 + q;
        int deg = g_deg[i];
        float sii = g_s2i[i];
        int idx[4]; float ev[4];
        float m = -1e30f;
        #pragma unroll
        for (int c4 = 0; c4 < 4; c4++) {
            int jj = c4 * 32 + lane;
            int j = 0;
            float e = -1e30f;
            if (jj < deg) {
                j = g_nbr[i * MAXDEG + jj];
                float xx = sii + g_s2j[j];
                e = (xx >= 0.f) ? xx : 0.2f * xx;
            }
            idx[c4] = j;
            ev[c4] = e;
            m = fmaxf(m, e);
        }
        #pragma unroll
        for (int o = 16; o; o >>= 1) m = fmaxf(m, __shfl_xor_sync(FULL, m, o));
        float s = 0.f;
        #pragma unroll
        for (int c4 = 0; c4 < 4; c4++) {
            int jj = c4 * 32 + lane;
            float wv = (jj < deg) ? __expf(ev[c4] - m) : 0.f;
            ev[c4] = wv;
            s += wv;
        }
        #pragma unroll
        for (int o = 16; o; o >>= 1) s += __shfl_xor_sync(FULL, s, o);
        float inv = 1.f / s;
        #pragma unroll
        for (int c4 = 0; c4 < 4; c4++) ev[c4] *= inv;

        float a0 = 0.f, a1 = 0.f;
        for (int jj = 0; jj < deg; jj++) {
            int cq = jj >> 5, l = jj & 31;
            float wgt;
            int j;
            if (cq == 0)      { wgt = __shfl_sync(FULL, ev[0], l); j = __shfl_sync(FULL, idx[0], l); }
            else if (cq == 1) { wgt = __shfl_sync(FULL, ev[1], l); j = __shfl_sync(FULL, idx[1], l); }
            else if (cq == 2) { wgt = __shfl_sync(FULL, ev[2], l); j = __shfl_sync(FULL, idx[2], l); }
            else              { wgt = __shfl_sync(FULL, ev[3], l); j = __shfl_sync(FULL, idx[3], l); }
            a0 += wgt * g_h2p[(size_t)j * C2 + lane];
            if (lane < Cc - 32) a1 += wgt * g_h2p[(size_t)j * C2 + 32 + lane];
        }
        out[(size_t)i * Cc + lane] = a0;
        if (lane < Cc - 32) out[(size_t)i * Cc + 32 + lane] = a1;
    }
}

// ---------------- launch -----------------------------------------------------
#define SMEM_MEGA ((2 * 128 * 36 + 2 * 32 * 72 + 4 * 128) * 4)   // 57344

extern "C" void kernel_launch(void* const* d_in, const int* in_sizes, int n_in,
                              void* d_out, int out_size) {
    const float*         x      = (const float*)d_in[0];
    const unsigned char* adj    = (const unsigned char*)d_in[1];
    const float*         W1     = (const float*)d_in[2];
    const float*         a1_src = (const float*)d_in[3];
    const float*         a1_dst = (const float*)d_in[4];
    const float*         W2     = (const float*)d_in[5];
    const float*         a2_src = (const float*)d_in[6];
    const float*         a2_dst = (const float*)d_in[7];
    float* out = (float*)d_out;

    static bool init = false;
    if (!init) {
        init = true;
        cudaFuncSetAttribute(k_mega, cudaFuncAttributeMaxDynamicSharedMemorySize, SMEM_MEGA);
    }

    k_mega<<<NB, 256, SMEM_MEGA>>>(x, adj, W1, a1_src, a1_dst,
                                   W2, a2_src, a2_dst, out);
}

// round 12
// speedup vs baseline: 1.0048x; 1.0048x over previous
#include <cuda_runtime.h>
#include <cuda_bf16.h>
#include <math.h>
#include <stdint.h>

#define Nn 4096
#define Ff 512
#define Dd 64
#define Hh 8
#define HD 512   // Hh*Dd
#define Cc 40
#define C2 64    // padded class dim
#define MAXDEG 128

// ---------------- scratch (static device globals; no allocation) -------------
__device__ int   g_deg[Nn];
__device__ int   g_nbr[Nn * MAXDEG];
__device__ float g_h[(size_t)Nn * HD];
__device__ float g_si[Hh * Nn];
__device__ float g_sj[Hh * Nn];
__device__ float g_x2[(size_t)Nn * HD];
__device__ float g_h2p[(size_t)Nn * C2];   // padded h2 (cols 40..63 are 0)
__device__ float g_s2i[Nn];
__device__ float g_s2j[Nn];
__device__ int   g_flag2[64];              // per-block ready flags (fused2)

// ---------------- helpers ----------------------------------------------------
__device__ __forceinline__ uint32_t f2tf(float x) {
    uint32_t r;
    asm("cvt.rna.tf32.f32 %0, %1;" : "=r"(r) : "f"(x));
    return r;
}
__device__ __forceinline__ void cp16(uint32_t dst_smem, const void* src) {
    asm volatile("cp.async.cg.shared.global [%0], [%1], 16;\n"
                 :: "r"(dst_smem), "l"(src) : "memory");
}
__device__ __forceinline__ void cp_commit() {
    asm volatile("cp.async.commit_group;\n" ::: "memory");
}
__device__ __forceinline__ void cp_wait1() {
    asm volatile("cp.async.wait_group 1;\n" ::: "memory");
}
__device__ __forceinline__ void cp_wait0() {
    asm volatile("cp.async.wait_group 0;\n" ::: "memory");
}
__device__ __forceinline__ void mma_tf32(float* c, uint32_t a0, uint32_t a1,
                                         uint32_t a2, uint32_t a3,
                                         uint32_t b0, uint32_t b1) {
    asm volatile(
        "mma.sync.aligned.m16n8k8.row.col.f32.tf32.tf32.f32 "
        "{%0,%1,%2,%3}, {%4,%5,%6,%7}, {%8,%9}, {%0,%1,%2,%3};"
        : "+f"(c[0]), "+f"(c[1]), "+f"(c[2]), "+f"(c[3])
        : "r"(a0), "r"(a1), "r"(a2), "r"(a3), "r"(b0), "r"(b1));
}

__device__ __forceinline__ int detect_mode(const unsigned char* adj) {
    if (adj[(size_t)Nn + 1] == 1) return 0;                               // u8
    if (((const uint16_t*)adj)[(size_t)Nn + 1] == 0x3F80u) return 3;      // bf16
    uint32_t v32 = ((const uint32_t*)adj)[(size_t)Nn + 1];
    if (v32 == 0x3F800000u) return 2;                                     // f32
    if (((const uint64_t*)adj)[(size_t)Nn + 1] == 0x3FF0000000000000ull) return 4; // f64
    return 1;                                                             // i32
}
__device__ __forceinline__ unsigned nz4(unsigned w) {
    unsigned c = 0;
    if (w & 0x000000FFu) c |= 1u;
    if (w & 0x0000FF00u) c |= 2u;
    if (w & 0x00FF0000u) c |= 4u;
    if (w & 0xFF000000u) c |= 8u;
    return c;
}

// --- TF32 GEMM tile (proven shape: warps 4(M) x 2(N), NF=4, 3xTF32) ----------
template <int BM, int BCH, int AVALID>
__device__ __forceinline__ void gemm_tile(
    const float* __restrict__ A, const float* __restrict__ Bp,
    float* __restrict__ Cm, int Nc, int row0, int col0,
    const float* __restrict__ avs, const float* __restrict__ avd,
    float* __restrict__ si_out, float* __restrict__ sj_out, float* sm)
{
    constexpr int K = 512;
    constexpr int WM = BM / 4;
    constexpr int MF = WM / 16;
    constexpr int NF = 4;
    constexpr int BROW = BCH * 4;

    float* As_  = sm;                       // [2][BM][36]
    float* Bs_  = sm + 2 * BM * 36;         // [2][32][72]
    float* s_si = Bs_ + 2 * 32 * 72;        // [2][BM]
    float* s_sj = s_si + 2 * BM;            // [2][BM]
    uint32_t smb = (uint32_t)__cvta_generic_to_shared(sm);
    uint32_t asb = smb;
    uint32_t bsb = smb + 2 * BM * 36 * 4;

    int t = threadIdx.x, lane = t & 31, wid = t >> 5;
    int warpM = wid & 3, warpN = wid >> 2;
    int gId = lane >> 2, tig = lane & 3;

    if (BCH < 16 && t < 64) {   // zero-pad Bs cols [BROW,72) for both stages
        float* rp = Bs_ + t * 72;
        #pragma unroll
        for (int c = BROW; c < 72; c++) rp[c] = 0.f;
    }

    float acc[MF][NF][4];
    #pragma unroll
    for (int i = 0; i < MF; i++)
        #pragma unroll
        for (int j = 0; j < NF; j++)
            #pragma unroll
            for (int q = 0; q < 4; q++) acc[i][j][q] = 0.f;

    auto issue = [&](int stage, int k0) {
        #pragma unroll
        for (int it = 0; it < BM * 8 / 256; it++) {
            int id = t + it * 256;
            int r = id >> 3, c = id & 7;
            cp16(asb + ((stage * BM + r) * 36 + c * 4) * 4,
                 A + (size_t)(row0 + r) * K + k0 + c * 4);
        }
        constexpr int TOT = 32 * BCH;
        #pragma unroll
        for (int it = 0; it < (TOT + 255) / 256; it++) {
            int id = t + it * 256;
            if (id < TOT) {
                int r = id / BCH, c = id % BCH;
                cp16(bsb + ((stage * 32 + r) * 72 + c * 4) * 4,
                     Bp + (size_t)(k0 + r) * BROW + c * 4);
            }
        }
        cp_commit();
    };

    issue(0, 0);
    for (int kt = 0; kt < K / 32; kt++) {
        int cur = kt & 1;
        if (kt + 1 < K / 32) { issue(cur ^ 1, (kt + 1) * 32); cp_wait1(); }
        else cp_wait0();
        __syncthreads();

        const float* Asc = As_ + cur * BM * 36;
        const float* Bsc = Bs_ + cur * 32 * 72;
        #pragma unroll
        for (int ks = 0; ks < 4; ks++) {
            int kk = ks * 8;
            uint32_t ah[MF][4], al[MF][4];
            #pragma unroll
            for (int mf = 0; mf < MF; mf++) {
                int m0 = warpM * WM + mf * 16 + gId;
                float f0 = Asc[m0 * 36 + kk + tig];
                float f1 = Asc[(m0 + 8) * 36 + kk + tig];
                float f2 = Asc[m0 * 36 + kk + tig + 4];
                float f3 = Asc[(m0 + 8) * 36 + kk + tig + 4];
                ah[mf][0] = f2tf(f0); al[mf][0] = f2tf(f0 - __uint_as_float(ah[mf][0]));
                ah[mf][1] = f2tf(f1); al[mf][1] = f2tf(f1 - __uint_as_float(ah[mf][1]));
                ah[mf][2] = f2tf(f2); al[mf][2] = f2tf(f2 - __uint_as_float(ah[mf][2]));
                ah[mf][3] = f2tf(f3); al[mf][3] = f2tf(f3 - __uint_as_float(ah[mf][3]));
            }
            uint32_t bh[NF][2], bl[NF][2];
            #pragma unroll
            for (int nf = 0; nf < NF; nf++) {
                int n0 = warpN * 32 + nf * 8 + gId;
                float g0 = Bsc[(kk + tig) * 72 + n0];
                float g1 = Bsc[(kk + tig + 4) * 72 + n0];
                bh[nf][0] = f2tf(g0); bl[nf][0] = f2tf(g0 - __uint_as_float(bh[nf][0]));
                bh[nf][1] = f2tf(g1); bl[nf][1] = f2tf(g1 - __uint_as_float(bh[nf][1]));
            }
            #pragma unroll
            for (int mf = 0; mf < MF; mf++)
                #pragma unroll
                for (int nf = 0; nf < NF; nf++) {
                    mma_tf32(acc[mf][nf], ah[mf][0], ah[mf][1], ah[mf][2], ah[mf][3],
                             bl[nf][0], bl[nf][1]);
                    mma_tf32(acc[mf][nf], al[mf][0], al[mf][1], al[mf][2], al[mf][3],
                             bh[nf][0], bh[nf][1]);
                    mma_tf32(acc[mf][nf], ah[mf][0], ah[mf][1], ah[mf][2], ah[mf][3],
                             bh[nf][0], bh[nf][1]);
                }
        }
        __syncthreads();
    }

    // ---- C store ----
    #pragma unroll
    for (int mf = 0; mf < MF; mf++) {
        int r0 = row0 + warpM * WM + mf * 16 + gId;
        #pragma unroll
        for (int nf = 0; nf < NF; nf++) {
            int c0 = col0 + warpN * 32 + nf * 8 + tig * 2;
            *(float2*)&Cm[(size_t)r0 * Nc + c0] = make_float2(acc[mf][nf][0], acc[mf][nf][1]);
            *(float2*)&Cm[(size_t)(r0 + 8) * Nc + c0] = make_float2(acc[mf][nf][2], acc[mf][nf][3]);
        }
    }

    // ---- fused row dots: si/sj ----
    const unsigned FULL = 0xffffffffu;
    float advals[NF][2], asvals[NF][2];
    #pragma unroll
    for (int nf = 0; nf < NF; nf++) {
        int c = warpN * 32 + nf * 8 + tig * 2;
        advals[nf][0] = (c < AVALID) ? avd[c] : 0.f;
        asvals[nf][0] = (c < AVALID) ? avs[c] : 0.f;
        advals[nf][1] = (c + 1 < AVALID) ? avd[c + 1] : 0.f;
        asvals[nf][1] = (c + 1 < AVALID) ? avs[c + 1] : 0.f;
    }
    #pragma unroll
    for (int mf = 0; mf < MF; mf++) {
        float rAi = 0.f, rAj = 0.f, rBi = 0.f, rBj = 0.f;
        #pragma unroll
        for (int nf = 0; nf < NF; nf++) {
            rAi += acc[mf][nf][0] * advals[nf][0] + acc[mf][nf][1] * advals[nf][1];
            rAj += acc[mf][nf][0] * asvals[nf][0] + acc[mf][nf][1] * asvals[nf][1];
            rBi += acc[mf][nf][2] * advals[nf][0] + acc[mf][nf][3] * advals[nf][1];
            rBj += acc[mf][nf][2] * asvals[nf][0] + acc[mf][nf][3] * asvals[nf][1];
        }
        #pragma unroll
        for (int o = 1; o <= 2; o <<= 1) {
            rAi += __shfl_xor_sync(FULL, rAi, o);
            rAj += __shfl_xor_sync(FULL, rAj, o);
            rBi += __shfl_xor_sync(FULL, rBi, o);
            rBj += __shfl_xor_sync(FULL, rBj, o);
        }
        if (tig == 0) {
            int r = warpM * WM + mf * 16 + gId;
            s_si[warpN * BM + r] = rAi;
            s_sj[warpN * BM + r] = rAj;
            s_si[warpN * BM + r + 8] = rBi;
            s_sj[warpN * BM + r + 8] = rBj;
        }
    }
    __syncthreads();
    if (t < BM) {
        si_out[row0 + t] = s_si[t] + s_si[BM + t];
        sj_out[row0 + t] = s_sj[t] + s_sj[BM + t];
    }
}

// ---------------- launch 1: GEMM1 (BM=128; R5-proven) ------------------------
__global__ __launch_bounds__(256) void k_gemm1(
    const float* __restrict__ x, const float* __restrict__ W1,
    const float* __restrict__ a1_src, const float* __restrict__ a1_dst)
{
    extern __shared__ float sm[];
    int head = blockIdx.x, rb = blockIdx.y;
    gemm_tile<128, 16, 64>(x, W1 + (size_t)head * Ff * Dd, g_h, HD,
                           rb * 128, head * 64,
                           a1_src + head * Dd, a1_dst + head * Dd,
                           g_si + head * Nn, g_sj + head * Nn, sm);
}

// ------- launch 2: layer-1 attention with INLINE adjacency-row build ---------
// One block per node i. Each thread scans 16 columns of adjacency row i
// (one uint4 in u8 mode), block-scan compacts into smem + g_nbr (for fused2).
__global__ __launch_bounds__(256) void k_layer1(const unsigned char* __restrict__ adj) {
    __shared__ int   nbr_sh[MAXDEG];
    __shared__ float w_sh[Hh][MAXDEG];
    __shared__ int   warp_tot[9];
    __shared__ int   s_deg;
    const unsigned FULL = 0xffffffffu;
    int i = blockIdx.x;
    int t = threadIdx.x, lane = t & 31, wid = t >> 5;
    if (i == 0 && t < 64) g_flag2[t] = 0;   // reset fused2 flags each call

    // ---- inline build: columns [16t, 16t+16) of row i ----
    {
        int mode = detect_mode(adj);
        unsigned msk = 0;
        if (mode == 0) {
            uint4 v = ((const uint4*)(adj + (size_t)i * Nn))[t];
            msk = nz4(v.x) | (nz4(v.y) << 4) | (nz4(v.z) << 8) | (nz4(v.w) << 12);
        } else if (mode == 1) {
            const int* r = (const int*)adj + (size_t)i * Nn + t * 16;
            #pragma unroll
            for (int q = 0; q < 16; q++) if (r[q] != 0) msk |= 1u << q;
        } else if (mode == 2) {
            const float* r = (const float*)adj + (size_t)i * Nn + t * 16;
            #pragma unroll
            for (int q = 0; q < 16; q++) if (r[q] != 0.f) msk |= 1u << q;
        } else if (mode == 3) {
            const uint16_t* r = (const uint16_t*)adj + (size_t)i * Nn + t * 16;
            #pragma unroll
            for (int q = 0; q < 16; q++) if (r[q] != 0) msk |= 1u << q;
        } else {
            const double* r = (const double*)adj + (size_t)i * Nn + t * 16;
            #pragma unroll
            for (int q = 0; q < 16; q++) if (r[q] != 0.0) msk |= 1u << q;
        }
        int c = __popc(msk);
        // warp inclusive scan
        int pref = c;
        #pragma unroll
        for (int o = 1; o < 32; o <<= 1) {
            int n = __shfl_up_sync(FULL, pref, o);
            if (lane >= o) pref += n;
        }
        if (lane == 31) warp_tot[wid] = pref;
        __syncthreads();
        if (t == 0) {
            int run = 0;
            #pragma unroll
            for (int wq = 0; wq < 8; wq++) { int v = warp_tot[wq]; warp_tot[wq] = run; run += v; }
            warp_tot[8] = run;
            s_deg = (run < MAXDEG) ? run : MAXDEG;
            g_deg[i] = s_deg;
        }
        __syncthreads();
        int base = warp_tot[wid] + pref - c;   // exclusive prefix for this thread
        int j0 = t * 16;
        unsigned mm = msk;
        int pos = base;
        while (mm) {
            int b2 = __ffs(mm) - 1;
            mm &= mm - 1;
            if (pos < MAXDEG) {
                nbr_sh[pos] = j0 + b2;
                g_nbr[i * MAXDEG + pos] = j0 + b2;   // for fused2's layer-2
            }
            pos++;
        }
    }
    __syncthreads();
    int deg = s_deg;

    // ---- per-head masked softmax (warp h) ----
    {
        int h = wid;
        float sii = g_si[h * Nn + i];
        float ev[4];
        float m = -1e30f;
        #pragma unroll
        for (int it = 0; it < 4; it++) {
            int jj = it * 32 + lane;
            float e = -1e30f;
            if (jj < deg) {
                float xx = sii + g_sj[h * Nn + nbr_sh[jj]];
                e = (xx >= 0.f) ? xx : 0.2f * xx;
            }
            ev[it] = e;
            m = fmaxf(m, e);
        }
        #pragma unroll
        for (int o = 16; o; o >>= 1) m = fmaxf(m, __shfl_xor_sync(FULL, m, o));
        float s = 0.f;
        #pragma unroll
        for (int it = 0; it < 4; it++) {
            int jj = it * 32 + lane;
            float w = (jj < deg) ? __expf(ev[it] - m) : 0.f;
            ev[it] = w;
            s += w;
        }
        #pragma unroll
        for (int o = 16; o; o >>= 1) s += __shfl_xor_sync(FULL, s, o);
        float inv = 1.f / s;
        #pragma unroll
        for (int it = 0; it < 4; it++) {
            int jj = it * 32 + lane;
            if (jj < deg) w_sh[h][jj] = ev[it] * inv;
        }
    }
    __syncthreads();

    // ---- aggregate + ELU ----
    {
        int h = t >> 5;
        float2 acc = make_float2(0.f, 0.f);
        const float* wrow = w_sh[h];
        #pragma unroll 4
        for (int jj = 0; jj < deg; jj++) {
            float w = wrow[jj];
            float2 v = *(const float2*)&g_h[(size_t)nbr_sh[jj] * HD + 2 * t];
            acc.x += w * v.x;
            acc.y += w * v.y;
        }
        float2 r;
        r.x = (acc.x > 0.f) ? acc.x : expm1f(acc.x);
        r.y = (acc.y > 0.f) ? acc.y : expm1f(acc.y);
        *(float2*)&g_x2[(size_t)i * HD + 2 * t] = r;
    }
}

// --------- launch 3: GEMM2 (BM=64, proven) + flags + layer-2 attention -------
__global__ __launch_bounds__(256) void k_fused2(
    const float* __restrict__ W2,
    const float* __restrict__ a2_src, const float* __restrict__ a2_dst,
    float* __restrict__ out)
{
    extern __shared__ float sm[];
    const unsigned FULL = 0xffffffffu;
    int b = blockIdx.x;
    int t = threadIdx.x, lane = t & 31, w = t >> 5;

    // phase A: h2p rows [64b, 64b+64), fused s2i/s2j
    gemm_tile<64, 10, Cc>(g_x2, W2, g_h2p, C2, b * 64, 0,
                          a2_src, a2_dst, g_s2i, g_s2j, sm);
    __threadfence();
    __syncthreads();
    if (t == 0) atomicExch(&g_flag2[b], 1);

    // phase B: layer-2 for this block's 64 nodes; 8 warps x 8 nodes each
    for (int q = 0; q < 8; q++) {
        int i = b * 64 + w * 8 + q;
        int deg = g_deg[i];
        float sii = g_s2i[i];
        int idx[4]; float ev[4];
        float m = -1e30f;
        #pragma unroll
        for (int c4 = 0; c4 < 4; c4++) {
            int jj = c4 * 32 + lane;
            int j = 0;
            float e = -1e30f;
            if (jj < deg) {
                j = g_nbr[i * MAXDEG + jj];
                volatile int* fl = &g_flag2[j >> 6];
                while (*fl == 0) __nanosleep(40);
                float xx = sii + g_s2j[j];
                e = (xx >= 0.f) ? xx : 0.2f * xx;
            }
            idx[c4] = j;
            ev[c4] = e;
            m = fmaxf(m, e);
        }
        #pragma unroll
        for (int o = 16; o; o >>= 1) m = fmaxf(m, __shfl_xor_sync(FULL, m, o));
        float s = 0.f;
        #pragma unroll
        for (int c4 = 0; c4 < 4; c4++) {
            int jj = c4 * 32 + lane;
            float wv = (jj < deg) ? __expf(ev[c4] - m) : 0.f;
            ev[c4] = wv;
            s += wv;
        }
        #pragma unroll
        for (int o = 16; o; o >>= 1) s += __shfl_xor_sync(FULL, s, o);
        float inv = 1.f / s;
        #pragma unroll
        for (int c4 = 0; c4 < 4; c4++) ev[c4] *= inv;

        float a0 = 0.f, a1 = 0.f;
        for (int jj = 0; jj < deg; jj++) {
            int cq = jj >> 5, l = jj & 31;
            float wgt;
            int j;
            if (cq == 0)      { wgt = __shfl_sync(FULL, ev[0], l); j = __shfl_sync(FULL, idx[0], l); }
            else if (cq == 1) { wgt = __shfl_sync(FULL, ev[1], l); j = __shfl_sync(FULL, idx[1], l); }
            else if (cq == 2) { wgt = __shfl_sync(FULL, ev[2], l); j = __shfl_sync(FULL, idx[2], l); }
            else              { wgt = __shfl_sync(FULL, ev[3], l); j = __shfl_sync(FULL, idx[3], l); }
            a0 += wgt * g_h2p[(size_t)j * C2 + lane];
            if (lane < Cc - 32) a1 += wgt * g_h2p[(size_t)j * C2 + 32 + lane];
        }
        out[(size_t)i * Cc + lane] = a0;
        if (lane < Cc - 32) out[(size_t)i * Cc + 32 + lane] = a1;
    }
}

// ---------------- launch -----------------------------------------------------
#define SMEM_G1 ((2 * 128 * 36 + 2 * 32 * 72 + 4 * 128) * 4)   // 57344
#define SMEM_F2 ((2 * 64 * 36 + 2 * 32 * 72 + 4 * 64) * 4)     // 37888

extern "C" void kernel_launch(void* const* d_in, const int* in_sizes, int n_in,
                              void* d_out, int out_size) {
    const float*         x      = (const float*)d_in[0];
    const unsigned char* adj    = (const unsigned char*)d_in[1];
    const float*         W1     = (const float*)d_in[2];
    const float*         a1_src = (const float*)d_in[3];
    const float*         a1_dst = (const float*)d_in[4];
    const float*         W2     = (const float*)d_in[5];
    const float*         a2_src = (const float*)d_in[6];
    const float*         a2_dst = (const float*)d_in[7];
    float* out = (float*)d_out;

    static bool init = false;
    if (!init) {
        init = true;
        cudaFuncSetAttribute(k_gemm1, cudaFuncAttributeMaxDynamicSharedMemorySize, SMEM_G1);
        cudaFuncSetAttribute(k_fused2, cudaFuncAttributeMaxDynamicSharedMemorySize, SMEM_F2);
    }

    k_gemm1<<<dim3(Hh, Nn / 128), 256, SMEM_G1>>>(x, W1, a1_src, a1_dst);
    k_layer1<<<Nn, 256>>>(adj);
    k_fused2<<<64, 256, SMEM_F2>>>(W2, a2_src, a2_dst, out);
}

// round 15
// speedup vs baseline: 1.2819x; 1.2758x over previous
#include <cuda_runtime.h>
#include <cuda_bf16.h>
#include <math.h>
#include <stdint.h>

#define Nn 4096
#define Ff 512
#define Dd 64
#define Hh 8
#define HD 512   // Hh*Dd
#define Cc 40
#define C2 64    // padded class dim
#define MAXDEG 128

// ---------------- scratch (static device globals; no allocation) -------------
__device__ int   g_deg[Nn];
__device__ int   g_nbr[Nn * MAXDEG];
__device__ float g_h[(size_t)Nn * HD];        // layer1 features fp32
__device__ float g_si[Hh * Nn];
__device__ float g_sj[Hh * Nn];
__device__ float g_h2p[(size_t)Nn * C2];      // padded h2 (cols 40..63 = 0)
__device__ float g_s2i[Nn];
__device__ float g_s2j[Nn];
__device__ int   g_flag2[64];
// bf16 split operands
__device__ __nv_bfloat16 g_xhi[(size_t)Nn * Ff],  g_xlo[(size_t)Nn * Ff];
__device__ __nv_bfloat16 g_W1Thi[Hh * Dd * Ff],   g_W1Tlo[Hh * Dd * Ff];   // [h][d][k]
__device__ __nv_bfloat16 g_W2Thi[C2 * Ff],        g_W2Tlo[C2 * Ff];        // [c][k]
__device__ __nv_bfloat16 g_x2hi[(size_t)Nn * HD], g_x2lo[(size_t)Nn * HD];

// ---------------- helpers ----------------------------------------------------
__device__ __forceinline__ uint4 ldg_stream(const uint4* p) { return __ldcs(p); }
__device__ __forceinline__ void cp16(uint32_t dst_smem, const void* src) {
    asm volatile("cp.async.cg.shared.global [%0], [%1], 16;\n"
                 :: "r"(dst_smem), "l"(src) : "memory");
}
__device__ __forceinline__ void cp_commit() {
    asm volatile("cp.async.commit_group;\n" ::: "memory");
}
__device__ __forceinline__ void cp_wait1() {
    asm volatile("cp.async.wait_group 1;\n" ::: "memory");
}
__device__ __forceinline__ void cp_wait0() {
    asm volatile("cp.async.wait_group 0;\n" ::: "memory");
}
__device__ __forceinline__ void mma_bf16(float* c, uint32_t a0, uint32_t a1,
                                         uint32_t a2, uint32_t a3,
                                         uint32_t b0, uint32_t b1) {
    asm volatile(
        "mma.sync.aligned.m16n8k16.row.col.f32.bf16.bf16.f32 "
        "{%0,%1,%2,%3}, {%4,%5,%6,%7}, {%8,%9}, {%0,%1,%2,%3};"
        : "+f"(c[0]), "+f"(c[1]), "+f"(c[2]), "+f"(c[3])
        : "r"(a0), "r"(a1), "r"(a2), "r"(a3), "r"(b0), "r"(b1));
}

__device__ __forceinline__ int detect_mode(const unsigned char* adj) {
    if (adj[(size_t)Nn + 1] == 1) return 0;                               // u8
    if (((const uint16_t*)adj)[(size_t)Nn + 1] == 0x3F80u) return 3;      // bf16
    uint32_t v32 = ((const uint32_t*)adj)[(size_t)Nn + 1];
    if (v32 == 0x3F800000u) return 2;                                     // f32
    if (((const uint64_t*)adj)[(size_t)Nn + 1] == 0x3FF0000000000000ull) return 4; // f64
    return 1;                                                             // i32
}
__device__ __forceinline__ unsigned nz4(unsigned w) {
    unsigned c = 0;
    if (w & 0x000000FFu) c |= 1u;
    if (w & 0x0000FF00u) c |= 2u;
    if (w & 0x00FF0000u) c |= 4u;
    if (w & 0xFF000000u) c |= 8u;
    return c;
}
__device__ __forceinline__ int emit_mask(int row, int cnt, unsigned msk,
                                         int j0, int lane) {
    const unsigned FULL = 0xffffffffu;
    int c = __popc(msk);
    int pref = c;
    #pragma unroll
    for (int o = 1; o < 32; o <<= 1) {
        int n = __shfl_up_sync(FULL, pref, o);
        if (lane >= o) pref += n;
    }
    int pos = cnt + pref - c;
    while (msk) {
        int b = __ffs(msk) - 1;
        msk &= msk - 1;
        if (pos < MAXDEG) g_nbr[row * MAXDEG + pos] = j0 + b;
        pos++;
    }
    return cnt + __shfl_sync(FULL, pref, 31);
}

__device__ void build_rows(const unsigned char* adj, int rb) {
    int row  = rb * 8 + (threadIdx.x >> 5);
    int lane = threadIdx.x & 31;
    int mode = detect_mode(adj);
    int cnt = 0;
    if (mode == 0) {
        const uint4* r = (const uint4*)(adj + (size_t)row * Nn);
        #pragma unroll
        for (int it = 0; it < Nn / 512; it++) {
            uint4 v = ldg_stream(&r[it * 32 + lane]);
            unsigned msk = nz4(v.x) | (nz4(v.y) << 4) | (nz4(v.z) << 8) | (nz4(v.w) << 12);
            cnt = emit_mask(row, cnt, msk, it * 512 + lane * 16, lane);
        }
    } else if (mode == 1 || mode == 2) {
        const uint4* r = (const uint4*)adj + (size_t)row * (Nn / 4);
        for (int it = 0; it < Nn / 128; it++) {
            uint4 v = ldg_stream(&r[it * 32 + lane]);
            unsigned msk = (v.x ? 1u : 0u) | (v.y ? 2u : 0u) | (v.z ? 4u : 0u) | (v.w ? 8u : 0u);
            cnt = emit_mask(row, cnt, msk, it * 128 + lane * 4, lane);
        }
    } else if (mode == 3) {
        const uint4* r = (const uint4*)adj + (size_t)row * (Nn / 8);
        for (int it = 0; it < Nn / 256; it++) {
            uint4 v = ldg_stream(&r[it * 32 + lane]);
            unsigned msk = 0;
            unsigned w[4] = {v.x, v.y, v.z, v.w};
            #pragma unroll
            for (int q = 0; q < 4; q++) {
                if (w[q] & 0x0000FFFFu) msk |= 1u << (2 * q);
                if (w[q] & 0xFFFF0000u) msk |= 2u << (2 * q);
            }
            cnt = emit_mask(row, cnt, msk, it * 256 + lane * 8, lane);
        }
    } else {
        const double* rd = (const double*)adj + (size_t)row * Nn;
        const unsigned FULL = 0xffffffffu;
        for (int base = 0; base < Nn; base += 32) {
            int j = base + lane;
            bool edge = rd[j] != 0.0;
            unsigned m = __ballot_sync(FULL, edge);
            if (edge) {
                int pos = cnt + __popc(m & ((1u << lane) - 1u));
                if (pos < MAXDEG) g_nbr[row * MAXDEG + pos] = j;
            }
            cnt += __popc(m);
        }
    }
    if (lane == 0) g_deg[row] = (cnt < MAXDEG) ? cnt : MAXDEG;
}

// ------ launch 1: adjacency build ∪ x-split ∪ W1/W2 transpose-splits ---------
__global__ __launch_bounds__(256) void k_prep(
    const unsigned char* __restrict__ adj, const float* __restrict__ x,
    const float* __restrict__ W1, const float* __restrict__ W2)
{
    __shared__ uint16_t sh_hi[64][72];
    __shared__ uint16_t sh_lo[64][72];
    int b = blockIdx.x, t = threadIdx.x;

    if (b < 512) {                       // adjacency: 8 rows per block
        build_rows(adj, b);
    } else if (b < 1536) {               // x split: 2048 elems per block
        size_t base = (size_t)(b - 512) * 2048 + t * 8;
        #pragma unroll
        for (int q = 0; q < 2; q++) {
            float4 v = *(const float4*)&x[base + q * 4];
            __nv_bfloat16 h0 = __float2bfloat16(v.x);
            __nv_bfloat16 h1 = __float2bfloat16(v.y);
            __nv_bfloat16 h2 = __float2bfloat16(v.z);
            __nv_bfloat16 h3 = __float2bfloat16(v.w);
            __nv_bfloat16 l0 = __float2bfloat16(v.x - __bfloat162float(h0));
            __nv_bfloat16 l1 = __float2bfloat16(v.y - __bfloat162float(h1));
            __nv_bfloat16 l2 = __float2bfloat16(v.z - __bfloat162float(h2));
            __nv_bfloat16 l3 = __float2bfloat16(v.w - __bfloat162float(h3));
            __nv_bfloat162* dh = (__nv_bfloat162*)&g_xhi[base + q * 4];
            __nv_bfloat162* dl = (__nv_bfloat162*)&g_xlo[base + q * 4];
            __nv_bfloat162 p;
            p.x = h0; p.y = h1; dh[0] = p;
            p.x = h2; p.y = h3; dh[1] = p;
            p.x = l0; p.y = l1; dl[0] = p;
            p.x = l2; p.y = l3; dl[1] = p;
        }
    } else if (b < 1608) {               // weight transpose+split: 72 blocks
        int mb = b - 1536;
        int mIdx = mb / 8, kt = mb % 8;
        const float* in;
        int nstride, nvalid;
        __nv_bfloat16 *oh, *ol;
        if (mIdx < 8) {
            in = W1 + (size_t)mIdx * Ff * Dd; nstride = Dd; nvalid = Dd;
            oh = g_W1Thi + (size_t)mIdx * Dd * Ff;
            ol = g_W1Tlo + (size_t)mIdx * Dd * Ff;
        } else {
            in = W2; nstride = Cc; nvalid = Cc;
            oh = g_W2Thi; ol = g_W2Tlo;
        }
        int k0 = kt * 64;
        #pragma unroll
        for (int it = 0; it < 16; it++) {
            int idx = it * 256 + t;
            int kk = idx >> 6, nn = idx & 63;
            float v = (nn < nvalid) ? in[(size_t)(k0 + kk) * nstride + nn] : 0.f;
            __nv_bfloat16 h = __float2bfloat16(v);
            __nv_bfloat16 l = __float2bfloat16(v - __bfloat162float(h));
            sh_hi[kk][nn] = __bfloat16_as_ushort(h);
            sh_lo[kk][nn] = __bfloat16_as_ushort(l);
        }
        __syncthreads();
        #pragma unroll
        for (int it = 0; it < 16; it++) {
            int idx = it * 256 + t;
            int nn = idx >> 6, kk = idx & 63;
            oh[(size_t)nn * Ff + k0 + kk] = __ushort_as_bfloat16(sh_hi[kk][nn]);
            ol[(size_t)nn * Ff + k0 + kk] = __ushort_as_bfloat16(sh_lo[kk][nn]);
        }
    }
}

// --- bf16 split GEMM tile: warps 4(M) x 2(N), mma.m16n8k16, 3 MMAs/pair ------
// C[row0:+BM, col0:+64] = (Ah+Al)(Bh+Bl)^T approx (missing lo*lo ~ 2^-16).
// A: [*, 512] bf16 rows; B: [n][512] bf16 rows (k-major, transposed weights).
// Epilogue row-dots into si/sj (cols < AVALID).
template <int BM, int AVALID>
__device__ __forceinline__ void gemm_bf16(
    const __nv_bfloat16* __restrict__ Ah, const __nv_bfloat16* __restrict__ Al,
    const __nv_bfloat16* __restrict__ Bh, const __nv_bfloat16* __restrict__ Bl,
    float* __restrict__ Cm, int Nc, int row0, int col0,
    const float* __restrict__ avs, const float* __restrict__ avd,
    float* __restrict__ si_out, float* __restrict__ sj_out, float* sm)
{
    constexpr int K = 512;
    constexpr int WM = BM / 4;
    constexpr int MF = WM / 16;
    constexpr int NF = 4;
    // word offsets in smem (uint32 = 2 bf16; 16 data words/row, stride 20)
    constexpr int A_LO = 2 * BM * 20;
    constexpr int B_HI = 4 * BM * 20;
    constexpr int B_LO = B_HI + 2 * 64 * 20;
    constexpr int S_SI = B_HI + 4 * 64 * 20;
    constexpr int S_SJ = S_SI + 2 * BM;

    uint32_t* smw = (uint32_t*)sm;
    float* s_si = sm + S_SI;
    float* s_sj = sm + S_SJ;
    uint32_t smb = (uint32_t)__cvta_generic_to_shared(sm);

    int t = threadIdx.x, lane = t & 31, wid = t >> 5;
    int warpM = wid & 3, warpN = wid >> 2;
    int gId = lane >> 2, tig = lane & 3;

    float acc[MF][NF][4];
    #pragma unroll
    for (int i = 0; i < MF; i++)
        #pragma unroll
        for (int j = 0; j < NF; j++)
            #pragma unroll
            for (int q = 0; q < 4; q++) acc[i][j][q] = 0.f;

    auto issue = [&](int stage, int k0) {
        // A tiles: BM rows x 32 k (64B = 4 chunks) per split
        #pragma unroll
        for (int it = 0; it < BM * 4 / 256; it++) {
            int id = t + it * 256;
            int r = id >> 2, c = id & 3;
            cp16(smb + ((stage * BM + r) * 20 + c * 4) * 4,
                 Ah + (size_t)(row0 + r) * K + k0 + c * 8);
            cp16(smb + (A_LO + (stage * BM + r) * 20 + c * 4) * 4,
                 Al + (size_t)(row0 + r) * K + k0 + c * 8);
        }
        // B tiles: 64 rows x 32 k per split (256 chunks -> 1 per thread)
        {
            int r = t >> 2, c = t & 3;
            cp16(smb + (B_HI + (stage * 64 + r) * 20 + c * 4) * 4,
                 Bh + (size_t)r * K + k0 + c * 8);
            cp16(smb + (B_LO + (stage * 64 + r) * 20 + c * 4) * 4,
                 Bl + (size_t)r * K + k0 + c * 8);
        }
        cp_commit();
    };

    issue(0, 0);
    for (int kt = 0; kt < K / 32; kt++) {
        int cur = kt & 1;
        if (kt + 1 < K / 32) { issue(cur ^ 1, (kt + 1) * 32); cp_wait1(); }
        else cp_wait0();
        __syncthreads();

        const uint32_t* Ahc = smw + cur * BM * 20;
        const uint32_t* Alc = smw + A_LO + cur * BM * 20;
        const uint32_t* Bhc = smw + B_HI + cur * 64 * 20;
        const uint32_t* Blc = smw + B_LO + cur * 64 * 20;
        #pragma unroll
        for (int ks = 0; ks < 2; ks++) {
            int ws = ks * 8;
            uint32_t ah[MF][4], al[MF][4];
            #pragma unroll
            for (int mf = 0; mf < MF; mf++) {
                int m0 = warpM * WM + mf * 16 + gId;
                ah[mf][0] = Ahc[m0 * 20 + ws + tig];
                ah[mf][1] = Ahc[(m0 + 8) * 20 + ws + tig];
                ah[mf][2] = Ahc[m0 * 20 + ws + tig + 4];
                ah[mf][3] = Ahc[(m0 + 8) * 20 + ws + tig + 4];
                al[mf][0] = Alc[m0 * 20 + ws + tig];
                al[mf][1] = Alc[(m0 + 8) * 20 + ws + tig];
                al[mf][2] = Alc[m0 * 20 + ws + tig + 4];
                al[mf][3] = Alc[(m0 + 8) * 20 + ws + tig + 4];
            }
            uint32_t bh[NF][2], bl[NF][2];
            #pragma unroll
            for (int nf = 0; nf < NF; nf++) {
                int n0 = warpN * 32 + nf * 8 + gId;
                bh[nf][0] = Bhc[n0 * 20 + ws + tig];
                bh[nf][1] = Bhc[n0 * 20 + ws + tig + 4];
                bl[nf][0] = Blc[n0 * 20 + ws + tig];
                bl[nf][1] = Blc[n0 * 20 + ws + tig + 4];
            }
            #pragma unroll
            for (int mf = 0; mf < MF; mf++)
                #pragma unroll
                for (int nf = 0; nf < NF; nf++) {
                    mma_bf16(acc[mf][nf], ah[mf][0], ah[mf][1], ah[mf][2], ah[mf][3],
                             bh[nf][0], bh[nf][1]);
                    mma_bf16(acc[mf][nf], ah[mf][0], ah[mf][1], ah[mf][2], ah[mf][3],
                             bl[nf][0], bl[nf][1]);
                    mma_bf16(acc[mf][nf], al[mf][0], al[mf][1], al[mf][2], al[mf][3],
                             bh[nf][0], bh[nf][1]);
                }
        }
        __syncthreads();
    }

    // ---- C store ----
    #pragma unroll
    for (int mf = 0; mf < MF; mf++) {
        int r0 = row0 + warpM * WM + mf * 16 + gId;
        #pragma unroll
        for (int nf = 0; nf < NF; nf++) {
            int c0 = col0 + warpN * 32 + nf * 8 + tig * 2;
            *(float2*)&Cm[(size_t)r0 * Nc + c0] = make_float2(acc[mf][nf][0], acc[mf][nf][1]);
            *(float2*)&Cm[(size_t)(r0 + 8) * Nc + c0] = make_float2(acc[mf][nf][2], acc[mf][nf][3]);
        }
    }

    // ---- fused row dots: si/sj ----
    const unsigned FULL = 0xffffffffu;
    float advals[NF][2], asvals[NF][2];
    #pragma unroll
    for (int nf = 0; nf < NF; nf++) {
        int c = warpN * 32 + nf * 8 + tig * 2;
        advals[nf][0] = (c < AVALID) ? avd[c] : 0.f;
        asvals[nf][0] = (c < AVALID) ? avs[c] : 0.f;
        advals[nf][1] = (c + 1 < AVALID) ? avd[c + 1] : 0.f;
        asvals[nf][1] = (c + 1 < AVALID) ? avs[c + 1] : 0.f;
    }
    #pragma unroll
    for (int mf = 0; mf < MF; mf++) {
        float rAi = 0.f, rAj = 0.f, rBi = 0.f, rBj = 0.f;
        #pragma unroll
        for (int nf = 0; nf < NF; nf++) {
            rAi += acc[mf][nf][0] * advals[nf][0] + acc[mf][nf][1] * advals[nf][1];
            rAj += acc[mf][nf][0] * asvals[nf][0] + acc[mf][nf][1] * asvals[nf][1];
            rBi += acc[mf][nf][2] * advals[nf][0] + acc[mf][nf][3] * advals[nf][1];
            rBj += acc[mf][nf][2] * asvals[nf][0] + acc[mf][nf][3] * asvals[nf][1];
        }
        #pragma unroll
        for (int o = 1; o <= 2; o <<= 1) {
            rAi += __shfl_xor_sync(FULL, rAi, o);
            rAj += __shfl_xor_sync(FULL, rAj, o);
            rBi += __shfl_xor_sync(FULL, rBi, o);
            rBj += __shfl_xor_sync(FULL, rBj, o);
        }
        if (tig == 0) {
            int r = warpM * WM + mf * 16 + gId;
            s_si[warpN * BM + r] = rAi;
            s_sj[warpN * BM + r] = rAj;
            s_si[warpN * BM + r + 8] = rBi;
            s_sj[warpN * BM + r + 8] = rBj;
        }
    }
    __syncthreads();
    if (t < BM) {
        si_out[row0 + t] = s_si[t] + s_si[BM + t];
        sj_out[row0 + t] = s_sj[t] + s_sj[BM + t];
    }
}

// ---------------- launch 2: GEMM1 bf16 (BM=128) ------------------------------
__global__ __launch_bounds__(256) void k_gemm1(
    const float* __restrict__ a1_src, const float* __restrict__ a1_dst)
{
    extern __shared__ float sm[];
    int head = blockIdx.x, rb = blockIdx.y;
    gemm_bf16<128, 64>(g_xhi, g_xlo,
                       g_W1Thi + (size_t)head * Dd * Ff,
                       g_W1Tlo + (size_t)head * Dd * Ff,
                       g_h, HD, rb * 128, head * 64,
                       a1_src + head * Dd, a1_dst + head * Dd,
                       g_si + head * Nn, g_sj + head * Nn, sm);
}

// ---------------- launch 3: layer-1 attention (standard, proven) -------------
__global__ __launch_bounds__(256) void k_layer1() {
    __shared__ int   nbr_sh[MAXDEG];
    __shared__ float w_sh[Hh][MAXDEG];
    const unsigned FULL = 0xffffffffu;
    int i = blockIdx.x;
    int deg = g_deg[i];
    int t = threadIdx.x, lane = t & 31, wid = t >> 5;
    if (i == 0 && t < 64) g_flag2[t] = 0;
    for (int jj = t; jj < deg; jj += 256) nbr_sh[jj] = g_nbr[i * MAXDEG + jj];
    __syncthreads();

    {
        int h = wid;
        float sii = g_si[h * Nn + i];
        float ev[4];
        float m = -1e30f;
        #pragma unroll
        for (int it = 0; it < 4; it++) {
            int jj = it * 32 + lane;
            float e = -1e30f;
            if (jj < deg) {
                float xx = sii + g_sj[h * Nn + nbr_sh[jj]];
                e = (xx >= 0.f) ? xx : 0.2f * xx;
            }
            ev[it] = e;
            m = fmaxf(m, e);
        }
        #pragma unroll
        for (int o = 16; o; o >>= 1) m = fmaxf(m, __shfl_xor_sync(FULL, m, o));
        float s = 0.f;
        #pragma unroll
        for (int it = 0; it < 4; it++) {
            int jj = it * 32 + lane;
            float w = (jj < deg) ? __expf(ev[it] - m) : 0.f;
            ev[it] = w;
            s += w;
        }
        #pragma unroll
        for (int o = 16; o; o >>= 1) s += __shfl_xor_sync(FULL, s, o);
        float inv = 1.f / s;
        #pragma unroll
        for (int it = 0; it < 4; it++) {
            int jj = it * 32 + lane;
            if (jj < deg) w_sh[h][jj] = ev[it] * inv;
        }
    }
    __syncthreads();

    {
        int h = t >> 5;
        float2 acc = make_float2(0.f, 0.f);
        const float* wrow = w_sh[h];
        #pragma unroll 4
        for (int jj = 0; jj < deg; jj++) {
            float w = wrow[jj];
            float2 v = *(const float2*)&g_h[(size_t)nbr_sh[jj] * HD + 2 * t];
            acc.x += w * v.x;
            acc.y += w * v.y;
        }
        float rx = (acc.x > 0.f) ? acc.x : expm1f(acc.x);
        float ry = (acc.y > 0.f) ? acc.y : expm1f(acc.y);
        // write x2 directly as bf16 hi/lo split (consumed only by GEMM2)
        __nv_bfloat16 hx = __float2bfloat16(rx);
        __nv_bfloat16 hy = __float2bfloat16(ry);
        __nv_bfloat16 lx = __float2bfloat16(rx - __bfloat162float(hx));
        __nv_bfloat16 ly = __float2bfloat16(ry - __bfloat162float(hy));
        __nv_bfloat162 ph; ph.x = hx; ph.y = hy;
        __nv_bfloat162 pl; pl.x = lx; pl.y = ly;
        ((__nv_bfloat162*)g_x2hi)[(size_t)i * 256 + t] = ph;
        ((__nv_bfloat162*)g_x2lo)[(size_t)i * 256 + t] = pl;
    }
}

// -------- launch 4: GEMM2 bf16 (BM=64, grid 64) + flags + layer-2 ------------
__global__ __launch_bounds__(256) void k_fused2(
    const float* __restrict__ a2_src, const float* __restrict__ a2_dst,
    float* __restrict__ out)
{
    extern __shared__ float sm[];
    const unsigned FULL = 0xffffffffu;
    int b = blockIdx.x;
    int t = threadIdx.x, lane = t & 31, w = t >> 5;

    gemm_bf16<64, Cc>(g_x2hi, g_x2lo, g_W2Thi, g_W2Tlo,
                      g_h2p, C2, b * 64, 0,
                      a2_src, a2_dst, g_s2i, g_s2j, sm);
    __threadfence();
    __syncthreads();
    if (t == 0) atomicExch(&g_flag2[b], 1);

    for (int q = 0; q < 8; q++) {
        int i = b * 64 + w * 8 + q;
        int deg = g_deg[i];
        float sii = g_s2i[i];
        int idx[4]; float ev[4];
        float m = -1e30f;
        #pragma unroll
        for (int c4 = 0; c4 < 4; c4++) {
            int jj = c4 * 32 + lane;
            int j = 0;
            float e = -1e30f;
            if (jj < deg) {
                j = g_nbr[i * MAXDEG + jj];
                volatile int* fl = &g_flag2[j >> 6];
                while (*fl == 0) __nanosleep(40);
                float xx = sii + g_s2j[j];
                e = (xx >= 0.f) ? xx : 0.2f * xx;
            }
            idx[c4] = j;
            ev[c4] = e;
            m = fmaxf(m, e);
        }
        #pragma unroll
        for (int o = 16; o; o >>= 1) m = fmaxf(m, __shfl_xor_sync(FULL, m, o));
        float s = 0.f;
        #pragma unroll
        for (int c4 = 0; c4 < 4; c4++) {
            int jj = c4 * 32 + lane;
            float wv = (jj < deg) ? __expf(ev[c4] - m) : 0.f;
            ev[c4] = wv;
            s += wv;
        }
        #pragma unroll
        for (int o = 16; o; o >>= 1) s += __shfl_xor_sync(FULL, s, o);
        float inv = 1.f / s;
        #pragma unroll
        for (int c4 = 0; c4 < 4; c4++) ev[c4] *= inv;

        float a0 = 0.f, a1 = 0.f;
        for (int jj = 0; jj < deg; jj++) {
            int cq = jj >> 5, l = jj & 31;
            float wgt;
            int j;
            if (cq == 0)      { wgt = __shfl_sync(FULL, ev[0], l); j = __shfl_sync(FULL, idx[0], l); }
            else if (cq == 1) { wgt = __shfl_sync(FULL, ev[1], l); j = __shfl_sync(FULL, idx[1], l); }
            else if (cq == 2) { wgt = __shfl_sync(FULL, ev[2], l); j = __shfl_sync(FULL, idx[2], l); }
            else              { wgt = __shfl_sync(FULL, ev[3], l); j = __shfl_sync(FULL, idx[3], l); }
            a0 += wgt * g_h2p[(size_t)j * C2 + lane];
            if (lane < Cc - 32) a1 += wgt * g_h2p[(size_t)j * C2 + 32 + lane];
        }
        out[(size_t)i * Cc + lane] = a0;
        if (lane < Cc - 32) out[(size_t)i * Cc + 32 + lane] = a1;
    }
}

// ---------------- launch -----------------------------------------------------
#define SMEM_G1 ((4 * 128 * 20 + 4 * 64 * 20 + 4 * 128) * 4)   // 63488
#define SMEM_F2 ((4 * 64 * 20 + 4 * 64 * 20 + 4 * 64) * 4)     // 41984

extern "C" void kernel_launch(void* const* d_in, const int* in_sizes, int n_in,
                              void* d_out, int out_size) {
    const float*         x      = (const float*)d_in[0];
    const unsigned char* adj    = (const unsigned char*)d_in[1];
    const float*         W1     = (const float*)d_in[2];
    const float*         a1_src = (const float*)d_in[3];
    const float*         a1_dst = (const float*)d_in[4];
    const float*         W2     = (const float*)d_in[5];
    const float*         a2_src = (const float*)d_in[6];
    const float*         a2_dst = (const float*)d_in[7];
    float* out = (float*)d_out;

    static bool init = false;
    if (!init) {
        init = true;
        cudaFuncSetAttribute(k_gemm1, cudaFuncAttributeMaxDynamicSharedMemorySize, SMEM_G1);
        cudaFuncSetAttribute(k_fused2, cudaFuncAttributeMaxDynamicSharedMemorySize, SMEM_F2);
    }

    k_prep<<<1608, 256>>>(adj, x, W1, W2);
    k_gemm1<<<dim3(Hh, Nn / 128), 256, SMEM_G1>>>(a1_src, a1_dst);
    k_layer1<<<Nn, 256>>>();
    k_fused2<<<64, 256, SMEM_F2>>>(a2_src, a2_dst, out);
}

// round 16
// speedup vs baseline: 1.7771x; 1.3864x over previous
#include <cuda_runtime.h>
#include <cuda_bf16.h>
#include <math.h>
#include <stdint.h>

#define Nn 4096
#define Ff 512
#define Dd 64
#define Hh 8
#define HD 512   // Hh*Dd
#define Cc 40
#define C2 64    // padded class dim
#define MAXDEG 128

// ---------------- scratch (static device globals; no allocation) -------------
__device__ int   g_deg[Nn];
__device__ int   g_nbr[Nn * MAXDEG];
__device__ float g_h[(size_t)Nn * HD];        // layer1 features fp32
__device__ float g_si[Hh * Nn];
__device__ float g_sj[Hh * Nn];
__device__ float g_h2p[(size_t)Nn * C2];      // padded h2 (cols 40..63 = 0)
__device__ float g_s2i[Nn];
__device__ float g_s2j[Nn];
// bf16 split operands
__device__ __nv_bfloat16 g_xhi[(size_t)Nn * Ff],  g_xlo[(size_t)Nn * Ff];
__device__ __nv_bfloat16 g_W1Thi[Hh * Dd * Ff],   g_W1Tlo[Hh * Dd * Ff];   // [h][d][k]
__device__ __nv_bfloat16 g_W2Thi[C2 * Ff],        g_W2Tlo[C2 * Ff];        // [c][k]
__device__ __nv_bfloat16 g_x2hi[(size_t)Nn * HD], g_x2lo[(size_t)Nn * HD];

// ---------------- helpers ----------------------------------------------------
__device__ __forceinline__ uint4 ldg_stream(const uint4* p) { return __ldcs(p); }
__device__ __forceinline__ void cp16(uint32_t dst_smem, const void* src) {
    asm volatile("cp.async.cg.shared.global [%0], [%1], 16;\n"
                 :: "r"(dst_smem), "l"(src) : "memory");
}
__device__ __forceinline__ void cp_commit() {
    asm volatile("cp.async.commit_group;\n" ::: "memory");
}
__device__ __forceinline__ void cp_wait1() {
    asm volatile("cp.async.wait_group 1;\n" ::: "memory");
}
__device__ __forceinline__ void cp_wait0() {
    asm volatile("cp.async.wait_group 0;\n" ::: "memory");
}
__device__ __forceinline__ void mma_bf16(float* c, uint32_t a0, uint32_t a1,
                                         uint32_t a2, uint32_t a3,
                                         uint32_t b0, uint32_t b1) {
    asm volatile(
        "mma.sync.aligned.m16n8k16.row.col.f32.bf16.bf16.f32 "
        "{%0,%1,%2,%3}, {%4,%5,%6,%7}, {%8,%9}, {%0,%1,%2,%3};"
        : "+f"(c[0]), "+f"(c[1]), "+f"(c[2]), "+f"(c[3])
        : "r"(a0), "r"(a1), "r"(a2), "r"(a3), "r"(b0), "r"(b1));
}

__device__ __forceinline__ int detect_mode(const unsigned char* adj) {
    if (adj[(size_t)Nn + 1] == 1) return 0;                               // u8
    if (((const uint16_t*)adj)[(size_t)Nn + 1] == 0x3F80u) return 3;      // bf16
    uint32_t v32 = ((const uint32_t*)adj)[(size_t)Nn + 1];
    if (v32 == 0x3F800000u) return 2;                                     // f32
    if (((const uint64_t*)adj)[(size_t)Nn + 1] == 0x3FF0000000000000ull) return 4; // f64
    return 1;                                                             // i32
}
__device__ __forceinline__ unsigned nz4(unsigned w) {
    unsigned c = 0;
    if (w & 0x000000FFu) c |= 1u;
    if (w & 0x0000FF00u) c |= 2u;
    if (w & 0x00FF0000u) c |= 4u;
    if (w & 0xFF000000u) c |= 8u;
    return c;
}
__device__ __forceinline__ int emit_mask(int row, int cnt, unsigned msk,
                                         int j0, int lane) {
    const unsigned FULL = 0xffffffffu;
    int c = __popc(msk);
    int pref = c;
    #pragma unroll
    for (int o = 1; o < 32; o <<= 1) {
        int n = __shfl_up_sync(FULL, pref, o);
        if (lane >= o) pref += n;
    }
    int pos = cnt + pref - c;
    while (msk) {
        int b = __ffs(msk) - 1;
        msk &= msk - 1;
        if (pos < MAXDEG) g_nbr[row * MAXDEG + pos] = j0 + b;
        pos++;
    }
    return cnt + __shfl_sync(FULL, pref, 31);
}

__device__ void build_rows(const unsigned char* adj, int rb) {
    int row  = rb * 8 + (threadIdx.x >> 5);
    int lane = threadIdx.x & 31;
    int mode = detect_mode(adj);
    int cnt = 0;
    if (mode == 0) {
        const uint4* r = (const uint4*)(adj + (size_t)row * Nn);
        #pragma unroll
        for (int it = 0; it < Nn / 512; it++) {
            uint4 v = ldg_stream(&r[it * 32 + lane]);
            unsigned msk = nz4(v.x) | (nz4(v.y) << 4) | (nz4(v.z) << 8) | (nz4(v.w) << 12);
            cnt = emit_mask(row, cnt, msk, it * 512 + lane * 16, lane);
        }
    } else if (mode == 1 || mode == 2) {
        const uint4* r = (const uint4*)adj + (size_t)row * (Nn / 4);
        for (int it = 0; it < Nn / 128; it++) {
            uint4 v = ldg_stream(&r[it * 32 + lane]);
            unsigned msk = (v.x ? 1u : 0u) | (v.y ? 2u : 0u) | (v.z ? 4u : 0u) | (v.w ? 8u : 0u);
            cnt = emit_mask(row, cnt, msk, it * 128 + lane * 4, lane);
        }
    } else if (mode == 3) {
        const uint4* r = (const uint4*)adj + (size_t)row * (Nn / 8);
        for (int it = 0; it < Nn / 256; it++) {
            uint4 v = ldg_stream(&r[it * 32 + lane]);
            unsigned msk = 0;
            unsigned w[4] = {v.x, v.y, v.z, v.w};
            #pragma unroll
            for (int q = 0; q < 4; q++) {
                if (w[q] & 0x0000FFFFu) msk |= 1u << (2 * q);
                if (w[q] & 0xFFFF0000u) msk |= 2u << (2 * q);
            }
            cnt = emit_mask(row, cnt, msk, it * 256 + lane * 8, lane);
        }
    } else {
        const double* rd = (const double*)adj + (size_t)row * Nn;
        const unsigned FULL = 0xffffffffu;
        for (int base = 0; base < Nn; base += 32) {
            int j = base + lane;
            bool edge = rd[j] != 0.0;
            unsigned m = __ballot_sync(FULL, edge);
            if (edge) {
                int pos = cnt + __popc(m & ((1u << lane) - 1u));
                if (pos < MAXDEG) g_nbr[row * MAXDEG + pos] = j;
            }
            cnt += __popc(m);
        }
    }
    if (lane == 0) g_deg[row] = (cnt < MAXDEG) ? cnt : MAXDEG;
}

// ------ launch 1: adjacency build ∪ x-split ∪ W1/W2 transpose-splits ---------
__global__ __launch_bounds__(256) void k_prep(
    const unsigned char* __restrict__ adj, const float* __restrict__ x,
    const float* __restrict__ W1, const float* __restrict__ W2)
{
    __shared__ uint16_t sh_hi[64][72];
    __shared__ uint16_t sh_lo[64][72];
    int b = blockIdx.x, t = threadIdx.x;

    if (b < 512) {                       // adjacency: 8 rows per block
        build_rows(adj, b);
    } else if (b < 1536) {               // x split: 2048 elems per block
        size_t base = (size_t)(b - 512) * 2048 + t * 8;
        #pragma unroll
        for (int q = 0; q < 2; q++) {
            float4 v = *(const float4*)&x[base + q * 4];
            __nv_bfloat16 h0 = __float2bfloat16(v.x);
            __nv_bfloat16 h1 = __float2bfloat16(v.y);
            __nv_bfloat16 h2 = __float2bfloat16(v.z);
            __nv_bfloat16 h3 = __float2bfloat16(v.w);
            __nv_bfloat16 l0 = __float2bfloat16(v.x - __bfloat162float(h0));
            __nv_bfloat16 l1 = __float2bfloat16(v.y - __bfloat162float(h1));
            __nv_bfloat16 l2 = __float2bfloat16(v.z - __bfloat162float(h2));
            __nv_bfloat16 l3 = __float2bfloat16(v.w - __bfloat162float(h3));
            __nv_bfloat162* dh = (__nv_bfloat162*)&g_xhi[base + q * 4];
            __nv_bfloat162* dl = (__nv_bfloat162*)&g_xlo[base + q * 4];
            __nv_bfloat162 p;
            p.x = h0; p.y = h1; dh[0] = p;
            p.x = h2; p.y = h3; dh[1] = p;
            p.x = l0; p.y = l1; dl[0] = p;
            p.x = l2; p.y = l3; dl[1] = p;
        }
    } else if (b < 1608) {               // weight transpose+split: 72 blocks
        int mb = b - 1536;
        int mIdx = mb / 8, kt = mb % 8;
        const float* in;
        int nstride, nvalid;
        __nv_bfloat16 *oh, *ol;
        if (mIdx < 8) {
            in = W1 + (size_t)mIdx * Ff * Dd; nstride = Dd; nvalid = Dd;
            oh = g_W1Thi + (size_t)mIdx * Dd * Ff;
            ol = g_W1Tlo + (size_t)mIdx * Dd * Ff;
        } else {
            in = W2; nstride = Cc; nvalid = Cc;
            oh = g_W2Thi; ol = g_W2Tlo;
        }
        int k0 = kt * 64;
        #pragma unroll
        for (int it = 0; it < 16; it++) {
            int idx = it * 256 + t;
            int kk = idx >> 6, nn = idx & 63;
            float v = (nn < nvalid) ? in[(size_t)(k0 + kk) * nstride + nn] : 0.f;
            __nv_bfloat16 h = __float2bfloat16(v);
            __nv_bfloat16 l = __float2bfloat16(v - __bfloat162float(h));
            sh_hi[kk][nn] = __bfloat16_as_ushort(h);
            sh_lo[kk][nn] = __bfloat16_as_ushort(l);
        }
        __syncthreads();
        #pragma unroll
        for (int it = 0; it < 16; it++) {
            int idx = it * 256 + t;
            int nn = idx >> 6, kk = idx & 63;
            oh[(size_t)nn * Ff + k0 + kk] = __ushort_as_bfloat16(sh_hi[kk][nn]);
            ol[(size_t)nn * Ff + k0 + kk] = __ushort_as_bfloat16(sh_lo[kk][nn]);
        }
    }
}

// --- bf16 split GEMM tile: warps 4(M) x 2(N), mma.m16n8k16, 3 MMAs/pair ------
template <int BM, int AVALID>
__device__ __forceinline__ void gemm_bf16(
    const __nv_bfloat16* __restrict__ Ah, const __nv_bfloat16* __restrict__ Al,
    const __nv_bfloat16* __restrict__ Bh, const __nv_bfloat16* __restrict__ Bl,
    float* __restrict__ Cm, int Nc, int row0, int col0,
    const float* __restrict__ avs, const float* __restrict__ avd,
    float* __restrict__ si_out, float* __restrict__ sj_out, float* sm)
{
    constexpr int K = 512;
    constexpr int WM = BM / 4;
    constexpr int MF = WM / 16;
    constexpr int NF = 4;
    constexpr int A_LO = 2 * BM * 20;
    constexpr int B_HI = 4 * BM * 20;
    constexpr int B_LO = B_HI + 2 * 64 * 20;
    constexpr int S_SI = B_HI + 4 * 64 * 20;
    constexpr int S_SJ = S_SI + 2 * BM;

    uint32_t* smw = (uint32_t*)sm;
    float* s_si = sm + S_SI;
    float* s_sj = sm + S_SJ;
    uint32_t smb = (uint32_t)__cvta_generic_to_shared(sm);

    int t = threadIdx.x, lane = t & 31, wid = t >> 5;
    int warpM = wid & 3, warpN = wid >> 2;
    int gId = lane >> 2, tig = lane & 3;

    float acc[MF][NF][4];
    #pragma unroll
    for (int i = 0; i < MF; i++)
        #pragma unroll
        for (int j = 0; j < NF; j++)
            #pragma unroll
            for (int q = 0; q < 4; q++) acc[i][j][q] = 0.f;

    auto issue = [&](int stage, int k0) {
        #pragma unroll
        for (int it = 0; it < BM * 4 / 256; it++) {
            int id = t + it * 256;
            int r = id >> 2, c = id & 3;
            cp16(smb + ((stage * BM + r) * 20 + c * 4) * 4,
                 Ah + (size_t)(row0 + r) * K + k0 + c * 8);
            cp16(smb + (A_LO + (stage * BM + r) * 20 + c * 4) * 4,
                 Al + (size_t)(row0 + r) * K + k0 + c * 8);
        }
        {
            int r = t >> 2, c = t & 3;
            cp16(smb + (B_HI + (stage * 64 + r) * 20 + c * 4) * 4,
                 Bh + (size_t)r * K + k0 + c * 8);
            cp16(smb + (B_LO + (stage * 64 + r) * 20 + c * 4) * 4,
                 Bl + (size_t)r * K + k0 + c * 8);
        }
        cp_commit();
    };

    issue(0, 0);
    for (int kt = 0; kt < K / 32; kt++) {
        int cur = kt & 1;
        if (kt + 1 < K / 32) { issue(cur ^ 1, (kt + 1) * 32); cp_wait1(); }
        else cp_wait0();
        __syncthreads();

        const uint32_t* Ahc = smw + cur * BM * 20;
        const uint32_t* Alc = smw + A_LO + cur * BM * 20;
        const uint32_t* Bhc = smw + B_HI + cur * 64 * 20;
        const uint32_t* Blc = smw + B_LO + cur * 64 * 20;
        #pragma unroll
        for (int ks = 0; ks < 2; ks++) {
            int ws = ks * 8;
            uint32_t ah[MF][4], al[MF][4];
            #pragma unroll
            for (int mf = 0; mf < MF; mf++) {
                int m0 = warpM * WM + mf * 16 + gId;
                ah[mf][0] = Ahc[m0 * 20 + ws + tig];
                ah[mf][1] = Ahc[(m0 + 8) * 20 + ws + tig];
                ah[mf][2] = Ahc[m0 * 20 + ws + tig + 4];
                ah[mf][3] = Ahc[(m0 + 8) * 20 + ws + tig + 4];
                al[mf][0] = Alc[m0 * 20 + ws + tig];
                al[mf][1] = Alc[(m0 + 8) * 20 + ws + tig];
                al[mf][2] = Alc[m0 * 20 + ws + tig + 4];
                al[mf][3] = Alc[(m0 + 8) * 20 + ws + tig + 4];
            }
            uint32_t bh[NF][2], bl[NF][2];
            #pragma unroll
            for (int nf = 0; nf < NF; nf++) {
                int n0 = warpN * 32 + nf * 8 + gId;
                bh[nf][0] = Bhc[n0 * 20 + ws + tig];
                bh[nf][1] = Bhc[n0 * 20 + ws + tig + 4];
                bl[nf][0] = Blc[n0 * 20 + ws + tig];
                bl[nf][1] = Blc[n0 * 20 + ws + tig + 4];
            }
            #pragma unroll
            for (int mf = 0; mf < MF; mf++)
                #pragma unroll
                for (int nf = 0; nf < NF; nf++) {
                    mma_bf16(acc[mf][nf], ah[mf][0], ah[mf][1], ah[mf][2], ah[mf][3],
                             bh[nf][0], bh[nf][1]);
                    mma_bf16(acc[mf][nf], ah[mf][0], ah[mf][1], ah[mf][2], ah[mf][3],
                             bl[nf][0], bl[nf][1]);
                    mma_bf16(acc[mf][nf], al[mf][0], al[mf][1], al[mf][2], al[mf][3],
                             bh[nf][0], bh[nf][1]);
                }
        }
        __syncthreads();
    }

    // ---- C store ----
    #pragma unroll
    for (int mf = 0; mf < MF; mf++) {
        int r0 = row0 + warpM * WM + mf * 16 + gId;
        #pragma unroll
        for (int nf = 0; nf < NF; nf++) {
            int c0 = col0 + warpN * 32 + nf * 8 + tig * 2;
            *(float2*)&Cm[(size_t)r0 * Nc + c0] = make_float2(acc[mf][nf][0], acc[mf][nf][1]);
            *(float2*)&Cm[(size_t)(r0 + 8) * Nc + c0] = make_float2(acc[mf][nf][2], acc[mf][nf][3]);
        }
    }

    // ---- fused row dots: si/sj ----
    const unsigned FULL = 0xffffffffu;
    float advals[NF][2], asvals[NF][2];
    #pragma unroll
    for (int nf = 0; nf < NF; nf++) {
        int c = warpN * 32 + nf * 8 + tig * 2;
        advals[nf][0] = (c < AVALID) ? avd[c] : 0.f;
        asvals[nf][0] = (c < AVALID) ? avs[c] : 0.f;
        advals[nf][1] = (c + 1 < AVALID) ? avd[c + 1] : 0.f;
        asvals[nf][1] = (c + 1 < AVALID) ? avs[c + 1] : 0.f;
    }
    #pragma unroll
    for (int mf = 0; mf < MF; mf++) {
        float rAi = 0.f, rAj = 0.f, rBi = 0.f, rBj = 0.f;
        #pragma unroll
        for (int nf = 0; nf < NF; nf++) {
            rAi += acc[mf][nf][0] * advals[nf][0] + acc[mf][nf][1] * advals[nf][1];
            rAj += acc[mf][nf][0] * asvals[nf][0] + acc[mf][nf][1] * asvals[nf][1];
            rBi += acc[mf][nf][2] * advals[nf][0] + acc[mf][nf][3] * advals[nf][1];
            rBj += acc[mf][nf][2] * asvals[nf][0] + acc[mf][nf][3] * asvals[nf][1];
        }
        #pragma unroll
        for (int o = 1; o <= 2; o <<= 1) {
            rAi += __shfl_xor_sync(FULL, rAi, o);
            rAj += __shfl_xor_sync(FULL, rAj, o);
            rBi += __shfl_xor_sync(FULL, rBi, o);
            rBj += __shfl_xor_sync(FULL, rBj, o);
        }
        if (tig == 0) {
            int r = warpM * WM + mf * 16 + gId;
            s_si[warpN * BM + r] = rAi;
            s_sj[warpN * BM + r] = rAj;
            s_si[warpN * BM + r + 8] = rBi;
            s_sj[warpN * BM + r + 8] = rBj;
        }
    }
    __syncthreads();
    if (t < BM) {
        si_out[row0 + t] = s_si[t] + s_si[BM + t];
        sj_out[row0 + t] = s_sj[t] + s_sj[BM + t];
    }
}

// ---------------- launch 2: GEMM1 bf16 (BM=128) ------------------------------
__global__ __launch_bounds__(256) void k_gemm1(
    const float* __restrict__ a1_src, const float* __restrict__ a1_dst)
{
    extern __shared__ float sm[];
    int head = blockIdx.x, rb = blockIdx.y;
    gemm_bf16<128, 64>(g_xhi, g_xlo,
                       g_W1Thi + (size_t)head * Dd * Ff,
                       g_W1Tlo + (size_t)head * Dd * Ff,
                       g_h, HD, rb * 128, head * 64,
                       a1_src + head * Dd, a1_dst + head * Dd,
                       g_si + head * Nn, g_sj + head * Nn, sm);
}

// ---------------- launch 3: layer-1 attention (proven) -----------------------
__global__ __launch_bounds__(256) void k_layer1() {
    __shared__ int   nbr_sh[MAXDEG];
    __shared__ float w_sh[Hh][MAXDEG];
    const unsigned FULL = 0xffffffffu;
    int i = blockIdx.x;
    int deg = g_deg[i];
    int t = threadIdx.x, lane = t & 31, wid = t >> 5;
    for (int jj = t; jj < deg; jj += 256) nbr_sh[jj] = g_nbr[i * MAXDEG + jj];
    __syncthreads();

    {
        int h = wid;
        float sii = g_si[h * Nn + i];
        float ev[4];
        float m = -1e30f;
        #pragma unroll
        for (int it = 0; it < 4; it++) {
            int jj = it * 32 + lane;
            float e = -1e30f;
            if (jj < deg) {
                float xx = sii + g_sj[h * Nn + nbr_sh[jj]];
                e = (xx >= 0.f) ? xx : 0.2f * xx;
            }
            ev[it] = e;
            m = fmaxf(m, e);
        }
        #pragma unroll
        for (int o = 16; o; o >>= 1) m = fmaxf(m, __shfl_xor_sync(FULL, m, o));
        float s = 0.f;
        #pragma unroll
        for (int it = 0; it < 4; it++) {
            int jj = it * 32 + lane;
            float w = (jj < deg) ? __expf(ev[it] - m) : 0.f;
            ev[it] = w;
            s += w;
        }
        #pragma unroll
        for (int o = 16; o; o >>= 1) s += __shfl_xor_sync(FULL, s, o);
        float inv = 1.f / s;
        #pragma unroll
        for (int it = 0; it < 4; it++) {
            int jj = it * 32 + lane;
            if (jj < deg) w_sh[h][jj] = ev[it] * inv;
        }
    }
    __syncthreads();

    {
        int h = t >> 5;
        float2 acc = make_float2(0.f, 0.f);
        const float* wrow = w_sh[h];
        #pragma unroll 4
        for (int jj = 0; jj < deg; jj++) {
            float w = wrow[jj];
            float2 v = *(const float2*)&g_h[(size_t)nbr_sh[jj] * HD + 2 * t];
            acc.x += w * v.x;
            acc.y += w * v.y;
        }
        float rx = (acc.x > 0.f) ? acc.x : expm1f(acc.x);
        float ry = (acc.y > 0.f) ? acc.y : expm1f(acc.y);
        __nv_bfloat16 hx = __float2bfloat16(rx);
        __nv_bfloat16 hy = __float2bfloat16(ry);
        __nv_bfloat16 lx = __float2bfloat16(rx - __bfloat162float(hx));
        __nv_bfloat16 ly = __float2bfloat16(ry - __bfloat162float(hy));
        __nv_bfloat162 ph; ph.x = hx; ph.y = hy;
        __nv_bfloat162 pl; pl.x = lx; pl.y = ly;
        ((__nv_bfloat162*)g_x2hi)[(size_t)i * 256 + t] = ph;
        ((__nv_bfloat162*)g_x2lo)[(size_t)i * 256 + t] = pl;
    }
}

// ---------------- launch 4: GEMM2 bf16 (BM=64, grid 64) ----------------------
__global__ __launch_bounds__(256) void k_gemm2(
    const float* __restrict__ a2_src, const float* __restrict__ a2_dst)
{
    extern __shared__ float sm[];
    int b = blockIdx.x;
    gemm_bf16<64, Cc>(g_x2hi, g_x2lo, g_W2Thi, g_W2Tlo,
                      g_h2p, C2, b * 64, 0,
                      a2_src, a2_dst, g_s2i, g_s2j, sm);
}

// ------------- launch 5: layer-2 attention (grid Nn, proven R5 form) ---------
__global__ __launch_bounds__(64) void k_layer2(float* __restrict__ out) {
    __shared__ int   nbr_sh[MAXDEG];
    __shared__ float w_sh[MAXDEG];
    const unsigned FULL = 0xffffffffu;
    int i = blockIdx.x, t = threadIdx.x, lane = t & 31;
    int deg = g_deg[i];
    for (int jj = t; jj < deg; jj += 64) nbr_sh[jj] = g_nbr[i * MAXDEG + jj];
    __syncthreads();
    if (t < 32) {
        float sii = g_s2i[i];
        float ev[4];
        float m = -1e30f;
        #pragma unroll
        for (int it = 0; it < 4; it++) {
            int jj = it * 32 + lane;
            float e = -1e30f;
            if (jj < deg) {
                float xx = sii + g_s2j[nbr_sh[jj]];
                e = (xx >= 0.f) ? xx : 0.2f * xx;
            }
            ev[it] = e;
            m = fmaxf(m, e);
        }
        #pragma unroll
        for (int o = 16; o; o >>= 1) m = fmaxf(m, __shfl_xor_sync(FULL, m, o));
        float s = 0.f;
        #pragma unroll
        for (int it = 0; it < 4; it++) {
            int jj = it * 32 + lane;
            float w = (jj < deg) ? __expf(ev[it] - m) : 0.f;
            ev[it] = w;
            s += w;
        }
        #pragma unroll
        for (int o = 16; o; o >>= 1) s += __shfl_xor_sync(FULL, s, o);
        float inv = 1.f / s;
        #pragma unroll
        for (int it = 0; it < 4; it++) {
            int jj = it * 32 + lane;
            if (jj < deg) w_sh[jj] = ev[it] * inv;
        }
    }
    __syncthreads();
    if (t < Cc) {
        float acc = 0.f;
        for (int jj = 0; jj < deg; jj++)
            acc += w_sh[jj] * g_h2p[(size_t)nbr_sh[jj] * C2 + t];
        out[(size_t)i * Cc + t] = acc;
    }
}

// ---------------- launch -----------------------------------------------------
#define SMEM_G1 ((4 * 128 * 20 + 4 * 64 * 20 + 4 * 128) * 4)   // 63488
#define SMEM_G2 ((4 * 64 * 20 + 4 * 64 * 20 + 4 * 64) * 4)     // 41984

extern "C" void kernel_launch(void* const* d_in, const int* in_sizes, int n_in,
                              void* d_out, int out_size) {
    const float*         x      = (const float*)d_in[0];
    const unsigned char* adj    = (const unsigned char*)d_in[1];
    const float*         W1     = (const float*)d_in[2];
    const float*         a1_src = (const float*)d_in[3];
    const float*         a1_dst = (const float*)d_in[4];
    const float*         W2     = (const float*)d_in[5];
    const float*         a2_src = (const float*)d_in[6];
    const float*         a2_dst = (const float*)d_in[7];
    float* out = (float*)d_out;

    static bool init = false;
    if (!init) {
        init = true;
        cudaFuncSetAttribute(k_gemm1, cudaFuncAttributeMaxDynamicSharedMemorySize, SMEM_G1);
        cudaFuncSetAttribute(k_gemm2, cudaFuncAttributeMaxDynamicSharedMemorySize, SMEM_G2);
    }

    k_prep<<<1608, 256>>>(adj, x, W1, W2);
    k_gemm1<<<dim3(Hh, Nn / 128), 256, SMEM_G1>>>(a1_src, a1_dst);
    k_layer1<<<Nn, 256>>>();
    k_gemm2<<<64, 256, SMEM_G2>>>(a2_src, a2_dst);
    k_layer2<<<Nn, 64>>>(out);
}

// round 17
// speedup vs baseline: 1.8182x; 1.0231x over previous
#include <cuda_runtime.h>
#include <cuda_bf16.h>
#include <math.h>
#include <stdint.h>

#define Nn 4096
#define Ff 512
#define Dd 64
#define Hh 8
#define HD 512   // Hh*Dd
#define Cc 40
#define C2 64    // padded class dim
#define MAXDEG 128

// ---------------- scratch (static device globals; no allocation) -------------
__device__ int   g_deg[Nn];
__device__ int   g_nbr[Nn * MAXDEG];
__device__ float g_h[(size_t)Nn * HD];        // layer1 features fp32
__device__ float g_si[Hh * Nn];
__device__ float g_sj[Hh * Nn];
__device__ float g_h2p[(size_t)Nn * C2];      // padded h2 (cols 40..63 = 0)
__device__ float g_s2i[Nn];
__device__ float g_s2j[Nn];
// bf16 split operands
__device__ __nv_bfloat16 g_xhi[(size_t)Nn * Ff],  g_xlo[(size_t)Nn * Ff];
__device__ __nv_bfloat16 g_W1Thi[Hh * Dd * Ff],   g_W1Tlo[Hh * Dd * Ff];   // [h][d][k]
__device__ __nv_bfloat16 g_W2Thi[C2 * Ff],        g_W2Tlo[C2 * Ff];        // [c][k]
__device__ __nv_bfloat16 g_x2hi[(size_t)Nn * HD], g_x2lo[(size_t)Nn * HD];

// ---------------- helpers ----------------------------------------------------
__device__ __forceinline__ uint4 ldg_stream(const uint4* p) { return __ldcs(p); }
__device__ __forceinline__ void cp16(uint32_t dst_smem, const void* src) {
    asm volatile("cp.async.cg.shared.global [%0], [%1], 16;\n"
                 :: "r"(dst_smem), "l"(src) : "memory");
}
__device__ __forceinline__ void cp_commit() {
    asm volatile("cp.async.commit_group;\n" ::: "memory");
}
__device__ __forceinline__ void cp_wait2() {
    asm volatile("cp.async.wait_group 2;\n" ::: "memory");
}
__device__ __forceinline__ void cp_wait1() {
    asm volatile("cp.async.wait_group 1;\n" ::: "memory");
}
__device__ __forceinline__ void cp_wait0() {
    asm volatile("cp.async.wait_group 0;\n" ::: "memory");
}
__device__ __forceinline__ void mma_bf16(float* c, uint32_t a0, uint32_t a1,
                                         uint32_t a2, uint32_t a3,
                                         uint32_t b0, uint32_t b1) {
    asm volatile(
        "mma.sync.aligned.m16n8k16.row.col.f32.bf16.bf16.f32 "
        "{%0,%1,%2,%3}, {%4,%5,%6,%7}, {%8,%9}, {%0,%1,%2,%3};"
        : "+f"(c[0]), "+f"(c[1]), "+f"(c[2]), "+f"(c[3])
        : "r"(a0), "r"(a1), "r"(a2), "r"(a3), "r"(b0), "r"(b1));
}
__device__ __forceinline__ void ldm_x4(uint32_t* r, uint32_t addr) {
    asm volatile("ldmatrix.sync.aligned.m8n8.x4.shared.b16 {%0,%1,%2,%3}, [%4];"
                 : "=r"(r[0]), "=r"(r[1]), "=r"(r[2]), "=r"(r[3]) : "r"(addr));
}
__device__ __forceinline__ void ldm_x2(uint32_t* r, uint32_t addr) {
    asm volatile("ldmatrix.sync.aligned.m8n8.x2.shared.b16 {%0,%1}, [%2];"
                 : "=r"(r[0]), "=r"(r[1]) : "r"(addr));
}

__device__ __forceinline__ int detect_mode(const unsigned char* adj) {
    if (adj[(size_t)Nn + 1] == 1) return 0;                               // u8
    if (((const uint16_t*)adj)[(size_t)Nn + 1] == 0x3F80u) return 3;      // bf16
    uint32_t v32 = ((const uint32_t*)adj)[(size_t)Nn + 1];
    if (v32 == 0x3F800000u) return 2;                                     // f32
    if (((const uint64_t*)adj)[(size_t)Nn + 1] == 0x3FF0000000000000ull) return 4; // f64
    return 1;                                                             // i32
}
__device__ __forceinline__ unsigned nz4(unsigned w) {
    unsigned c = 0;
    if (w & 0x000000FFu) c |= 1u;
    if (w & 0x0000FF00u) c |= 2u;
    if (w & 0x00FF0000u) c |= 4u;
    if (w & 0xFF000000u) c |= 8u;
    return c;
}
__device__ __forceinline__ int emit_mask(int row, int cnt, unsigned msk,
                                         int j0, int lane) {
    const unsigned FULL = 0xffffffffu;
    int c = __popc(msk);
    int pref = c;
    #pragma unroll
    for (int o = 1; o < 32; o <<= 1) {
        int n = __shfl_up_sync(FULL, pref, o);
        if (lane >= o) pref += n;
    }
    int pos = cnt + pref - c;
    while (msk) {
        int b = __ffs(msk) - 1;
        msk &= msk - 1;
        if (pos < MAXDEG) g_nbr[row * MAXDEG + pos] = j0 + b;
        pos++;
    }
    return cnt + __shfl_sync(FULL, pref, 31);
}

__device__ void build_rows(const unsigned char* adj, int rb) {
    int row  = rb * 8 + (threadIdx.x >> 5);
    int lane = threadIdx.x & 31;
    int mode = detect_mode(adj);
    int cnt = 0;
    if (mode == 0) {
        const uint4* r = (const uint4*)(adj + (size_t)row * Nn);
        #pragma unroll
        for (int it = 0; it < Nn / 512; it++) {
            uint4 v = ldg_stream(&r[it * 32 + lane]);
            unsigned msk = nz4(v.x) | (nz4(v.y) << 4) | (nz4(v.z) << 8) | (nz4(v.w) << 12);
            cnt = emit_mask(row, cnt, msk, it * 512 + lane * 16, lane);
        }
    } else if (mode == 1 || mode == 2) {
        const uint4* r = (const uint4*)adj + (size_t)row * (Nn / 4);
        for (int it = 0; it < Nn / 128; it++) {
            uint4 v = ldg_stream(&r[it * 32 + lane]);
            unsigned msk = (v.x ? 1u : 0u) | (v.y ? 2u : 0u) | (v.z ? 4u : 0u) | (v.w ? 8u : 0u);
            cnt = emit_mask(row, cnt, msk, it * 128 + lane * 4, lane);
        }
    } else if (mode == 3) {
        const uint4* r = (const uint4*)adj + (size_t)row * (Nn / 8);
        for (int it = 0; it < Nn / 256; it++) {
            uint4 v = ldg_stream(&r[it * 32 + lane]);
            unsigned msk = 0;
            unsigned w[4] = {v.x, v.y, v.z, v.w};
            #pragma unroll
            for (int q = 0; q < 4; q++) {
                if (w[q] & 0x0000FFFFu) msk |= 1u << (2 * q);
                if (w[q] & 0xFFFF0000u) msk |= 2u << (2 * q);
            }
            cnt = emit_mask(row, cnt, msk, it * 256 + lane * 8, lane);
        }
    } else {
        const double* rd = (const double*)adj + (size_t)row * Nn;
        const unsigned FULL = 0xffffffffu;
        for (int base = 0; base < Nn; base += 32) {
            int j = base + lane;
            bool edge = rd[j] != 0.0;
            unsigned m = __ballot_sync(FULL, edge);
            if (edge) {
                int pos = cnt + __popc(m & ((1u << lane) - 1u));
                if (pos < MAXDEG) g_nbr[row * MAXDEG + pos] = j;
            }
            cnt += __popc(m);
        }
    }
    if (lane == 0) g_deg[row] = (cnt < MAXDEG) ? cnt : MAXDEG;
}

// ------ launch 1: adjacency build ∪ x-split ∪ W1/W2 transpose-splits ---------
__global__ __launch_bounds__(256) void k_prep(
    const unsigned char* __restrict__ adj, const float* __restrict__ x,
    const float* __restrict__ W1, const float* __restrict__ W2)
{
    __shared__ uint16_t sh_hi[64][72];
    __shared__ uint16_t sh_lo[64][72];
    int b = blockIdx.x, t = threadIdx.x;

    if (b < 512) {
        build_rows(adj, b);
    } else if (b < 1536) {
        size_t base = (size_t)(b - 512) * 2048 + t * 8;
        #pragma unroll
        for (int q = 0; q < 2; q++) {
            float4 v = *(const float4*)&x[base + q * 4];
            __nv_bfloat16 h0 = __float2bfloat16(v.x);
            __nv_bfloat16 h1 = __float2bfloat16(v.y);
            __nv_bfloat16 h2 = __float2bfloat16(v.z);
            __nv_bfloat16 h3 = __float2bfloat16(v.w);
            __nv_bfloat16 l0 = __float2bfloat16(v.x - __bfloat162float(h0));
            __nv_bfloat16 l1 = __float2bfloat16(v.y - __bfloat162float(h1));
            __nv_bfloat16 l2 = __float2bfloat16(v.z - __bfloat162float(h2));
            __nv_bfloat16 l3 = __float2bfloat16(v.w - __bfloat162float(h3));
            __nv_bfloat162* dh = (__nv_bfloat162*)&g_xhi[base + q * 4];
            __nv_bfloat162* dl = (__nv_bfloat162*)&g_xlo[base + q * 4];
            __nv_bfloat162 p;
            p.x = h0; p.y = h1; dh[0] = p;
            p.x = h2; p.y = h3; dh[1] = p;
            p.x = l0; p.y = l1; dl[0] = p;
            p.x = l2; p.y = l3; dl[1] = p;
        }
    } else if (b < 1608) {
        int mb = b - 1536;
        int mIdx = mb / 8, kt = mb % 8;
        const float* in;
        int nstride, nvalid;
        __nv_bfloat16 *oh, *ol;
        if (mIdx < 8) {
            in = W1 + (size_t)mIdx * Ff * Dd; nstride = Dd; nvalid = Dd;
            oh = g_W1Thi + (size_t)mIdx * Dd * Ff;
            ol = g_W1Tlo + (size_t)mIdx * Dd * Ff;
        } else {
            in = W2; nstride = Cc; nvalid = Cc;
            oh = g_W2Thi; ol = g_W2Tlo;
        }
        int k0 = kt * 64;
        #pragma unroll
        for (int it = 0; it < 16; it++) {
            int idx = it * 256 + t;
            int kk = idx >> 6, nn = idx & 63;
            float v = (nn < nvalid) ? in[(size_t)(k0 + kk) * nstride + nn] : 0.f;
            __nv_bfloat16 h = __float2bfloat16(v);
            __nv_bfloat16 l = __float2bfloat16(v - __bfloat162float(h));
            sh_hi[kk][nn] = __bfloat16_as_ushort(h);
            sh_lo[kk][nn] = __bfloat16_as_ushort(l);
        }
        __syncthreads();
        #pragma unroll
        for (int it = 0; it < 16; it++) {
            int idx = it * 256 + t;
            int nn = idx >> 6, kk = idx & 63;
            oh[(size_t)nn * Ff + k0 + kk] = __ushort_as_bfloat16(sh_hi[kk][nn]);
            ol[(size_t)nn * Ff + k0 + kk] = __ushort_as_bfloat16(sh_lo[kk][nn]);
        }
    }
}

// --- bf16 split GEMM: 4(M)x2(N) warps, ldmatrix frags, 3-stage cp.async ------
template <int BM, int AVALID>
__device__ __forceinline__ void gemm_bf16(
    const __nv_bfloat16* __restrict__ Ah, const __nv_bfloat16* __restrict__ Al,
    const __nv_bfloat16* __restrict__ Bh, const __nv_bfloat16* __restrict__ Bl,
    float* __restrict__ Cm, int Nc, int row0, int col0,
    const float* __restrict__ avs, const float* __restrict__ avd,
    float* __restrict__ si_out, float* __restrict__ sj_out, float* sm)
{
    constexpr int K = 512;
    constexpr int NT = K / 32;             // 16 k-tiles
    constexpr int WM = BM / 4;
    constexpr int MF = WM / 16;
    constexpr int NF = 4;
    // words per stage: [Ahi BM*20][Alo BM*20][Bhi 64*20][Blo 64*20]
    constexpr int AW = BM * 20;
    constexpr int BW = 64 * 20;
    constexpr int STW = 2 * AW + 2 * BW;
    constexpr int S_SI = 3 * STW;
    constexpr int S_SJ = S_SI + 2 * BM;

    uint32_t* smw = (uint32_t*)sm;
    float* s_si = sm + S_SI;
    float* s_sj = sm + S_SJ;
    uint32_t smb = (uint32_t)__cvta_generic_to_shared(sm);

    int t = threadIdx.x, lane = t & 31, wid = t >> 5;
    int warpM = wid & 3, warpN = wid >> 2;
    int gId = lane >> 2, tig = lane & 3;

    float acc[MF][NF][4];
    #pragma unroll
    for (int i = 0; i < MF; i++)
        #pragma unroll
        for (int j = 0; j < NF; j++)
            #pragma unroll
            for (int q = 0; q < 4; q++) acc[i][j][q] = 0.f;

    auto issue = [&](int stage, int k0) {
        #pragma unroll
        for (int it = 0; it < BM * 4 / 256; it++) {
            int id = t + it * 256;
            int r = id >> 2, c = id & 3;
            cp16(smb + (stage * STW + r * 20 + c * 4) * 4,
                 Ah + (size_t)(row0 + r) * K + k0 + c * 8);
            cp16(smb + (stage * STW + AW + r * 20 + c * 4) * 4,
                 Al + (size_t)(row0 + r) * K + k0 + c * 8);
        }
        {
            int r = t >> 2, c = t & 3;
            cp16(smb + (stage * STW + 2 * AW + r * 20 + c * 4) * 4,
                 Bh + (size_t)r * K + k0 + c * 8);
            cp16(smb + (stage * STW + 2 * AW + BW + r * 20 + c * 4) * 4,
                 Bl + (size_t)r * K + k0 + c * 8);
        }
        cp_commit();
    };

    // ldmatrix lane-address components (constant across k-tiles)
    int a_row = (lane & 7) + ((lane >> 3) & 1) * 8;   // 0..15
    int a_col = (lane >> 4) * 4;                      // word offset 0 or 4
    int b_row = lane & 7;
    int b_col = ((lane >> 3) & 1) * 4;                // words 0 or 4 (lanes 0-15 used)

    issue(0, 0);
    issue(1, 32);
    for (int kt = 0; kt < NT; kt++) {
        int cur = kt % 3;
        if (kt + 2 < NT) { issue((kt + 2) % 3, (kt + 2) * 32); cp_wait2(); }
        else if (kt + 1 < NT) cp_wait1();
        else cp_wait0();
        __syncthreads();

        uint32_t baseA = smb + (cur * STW) * 4;
        uint32_t baseB = smb + (cur * STW + 2 * AW) * 4;
        #pragma unroll
        for (int ks = 0; ks < 2; ks++) {
            uint32_t ah[MF][4], al[MF][4];
            #pragma unroll
            for (int mf = 0; mf < MF; mf++) {
                uint32_t ad = baseA + ((warpM * WM + mf * 16 + a_row) * 20 + ks * 8 + a_col) * 4;
                ldm_x4(ah[mf], ad);
                ldm_x4(al[mf], ad + AW * 4);
            }
            uint32_t bh[NF][2], bl[NF][2];
            #pragma unroll
            for (int nf = 0; nf < NF; nf++) {
                uint32_t bd = baseB + ((warpN * 32 + nf * 8 + b_row) * 20 + ks * 8 + b_col) * 4;
                ldm_x2(bh[nf], bd);
                ldm_x2(bl[nf], bd + BW * 4);
            }
            #pragma unroll
            for (int mf = 0; mf < MF; mf++)
                #pragma unroll
                for (int nf = 0; nf < NF; nf++) {
                    mma_bf16(acc[mf][nf], ah[mf][0], ah[mf][1], ah[mf][2], ah[mf][3],
                             bh[nf][0], bh[nf][1]);
                    mma_bf16(acc[mf][nf], ah[mf][0], ah[mf][1], ah[mf][2], ah[mf][3],
                             bl[nf][0], bl[nf][1]);
                    mma_bf16(acc[mf][nf], al[mf][0], al[mf][1], al[mf][2], al[mf][3],
                             bh[nf][0], bh[nf][1]);
                }
        }
        __syncthreads();
    }

    // ---- C store ----
    #pragma unroll
    for (int mf = 0; mf < MF; mf++) {
        int r0 = row0 + warpM * WM + mf * 16 + gId;
        #pragma unroll
        for (int nf = 0; nf < NF; nf++) {
            int c0 = col0 + warpN * 32 + nf * 8 + tig * 2;
            *(float2*)&Cm[(size_t)r0 * Nc + c0] = make_float2(acc[mf][nf][0], acc[mf][nf][1]);
            *(float2*)&Cm[(size_t)(r0 + 8) * Nc + c0] = make_float2(acc[mf][nf][2], acc[mf][nf][3]);
        }
    }

    // ---- fused row dots: si/sj ----
    const unsigned FULL = 0xffffffffu;
    float advals[NF][2], asvals[NF][2];
    #pragma unroll
    for (int nf = 0; nf < NF; nf++) {
        int c = warpN * 32 + nf * 8 + tig * 2;
        advals[nf][0] = (c < AVALID) ? avd[c] : 0.f;
        asvals[nf][0] = (c < AVALID) ? avs[c] : 0.f;
        advals[nf][1] = (c + 1 < AVALID) ? avd[c + 1] : 0.f;
        asvals[nf][1] = (c + 1 < AVALID) ? avs[c + 1] : 0.f;
    }
    #pragma unroll
    for (int mf = 0; mf < MF; mf++) {
        float rAi = 0.f, rAj = 0.f, rBi = 0.f, rBj = 0.f;
        #pragma unroll
        for (int nf = 0; nf < NF; nf++) {
            rAi += acc[mf][nf][0] * advals[nf][0] + acc[mf][nf][1] * advals[nf][1];
            rAj += acc[mf][nf][0] * asvals[nf][0] + acc[mf][nf][1] * asvals[nf][1];
            rBi += acc[mf][nf][2] * advals[nf][0] + acc[mf][nf][3] * advals[nf][1];
            rBj += acc[mf][nf][2] * asvals[nf][0] + acc[mf][nf][3] * asvals[nf][1];
        }
        #pragma unroll
        for (int o = 1; o <= 2; o <<= 1) {
            rAi += __shfl_xor_sync(FULL, rAi, o);
            rAj += __shfl_xor_sync(FULL, rAj, o);
            rBi += __shfl_xor_sync(FULL, rBi, o);
            rBj += __shfl_xor_sync(FULL, rBj, o);
        }
        if (tig == 0) {
            int r = warpM * WM + mf * 16 + gId;
            s_si[warpN * BM + r] = rAi;
            s_sj[warpN * BM + r] = rAj;
            s_si[warpN * BM + r + 8] = rBi;
            s_sj[warpN * BM + r + 8] = rBj;
        }
    }
    __syncthreads();
    if (t < BM) {
        si_out[row0 + t] = s_si[t] + s_si[BM + t];
        sj_out[row0 + t] = s_sj[t] + s_sj[BM + t];
    }
}

// ---------------- launch 2: GEMM1 bf16 (BM=128) ------------------------------
__global__ __launch_bounds__(256) void k_gemm1(
    const float* __restrict__ a1_src, const float* __restrict__ a1_dst)
{
    extern __shared__ float sm[];
    int head = blockIdx.x, rb = blockIdx.y;
    gemm_bf16<128, 64>(g_xhi, g_xlo,
                       g_W1Thi + (size_t)head * Dd * Ff,
                       g_W1Tlo + (size_t)head * Dd * Ff,
                       g_h, HD, rb * 128, head * 64,
                       a1_src + head * Dd, a1_dst + head * Dd,
                       g_si + head * Nn, g_sj + head * Nn, sm);
}

// ---------------- launch 3: layer-1 attention (proven) -----------------------
__global__ __launch_bounds__(256) void k_layer1() {
    __shared__ int   nbr_sh[MAXDEG];
    __shared__ float w_sh[Hh][MAXDEG];
    const unsigned FULL = 0xffffffffu;
    int i = blockIdx.x;
    int deg = g_deg[i];
    int t = threadIdx.x, lane = t & 31, wid = t >> 5;
    for (int jj = t; jj < deg; jj += 256) nbr_sh[jj] = g_nbr[i * MAXDEG + jj];
    __syncthreads();

    {
        int h = wid;
        float sii = g_si[h * Nn + i];
        float ev[4];
        float m = -1e30f;
        #pragma unroll
        for (int it = 0; it < 4; it++) {
            int jj = it * 32 + lane;
            float e = -1e30f;
            if (jj < deg) {
                float xx = sii + g_sj[h * Nn + nbr_sh[jj]];
                e = (xx >= 0.f) ? xx : 0.2f * xx;
            }
            ev[it] = e;
            m = fmaxf(m, e);
        }
        #pragma unroll
        for (int o = 16; o; o >>= 1) m = fmaxf(m, __shfl_xor_sync(FULL, m, o));
        float s = 0.f;
        #pragma unroll
        for (int it = 0; it < 4; it++) {
            int jj = it * 32 + lane;
            float w = (jj < deg) ? __expf(ev[it] - m) : 0.f;
            ev[it] = w;
            s += w;
        }
        #pragma unroll
        for (int o = 16; o; o >>= 1) s += __shfl_xor_sync(FULL, s, o);
        float inv = 1.f / s;
        #pragma unroll
        for (int it = 0; it < 4; it++) {
            int jj = it * 32 + lane;
            if (jj < deg) w_sh[h][jj] = ev[it] * inv;
        }
    }
    __syncthreads();

    {
        int h = t >> 5;
        float2 acc = make_float2(0.f, 0.f);
        const float* wrow = w_sh[h];
        #pragma unroll 4
        for (int jj = 0; jj < deg; jj++) {
            float w = wrow[jj];
            float2 v = *(const float2*)&g_h[(size_t)nbr_sh[jj] * HD + 2 * t];
            acc.x += w * v.x;
            acc.y += w * v.y;
        }
        float rx = (acc.x > 0.f) ? acc.x : expm1f(acc.x);
        float ry = (acc.y > 0.f) ? acc.y : expm1f(acc.y);
        __nv_bfloat16 hx = __float2bfloat16(rx);
        __nv_bfloat16 hy = __float2bfloat16(ry);
        __nv_bfloat16 lx = __float2bfloat16(rx - __bfloat162float(hx));
        __nv_bfloat16 ly = __float2bfloat16(ry - __bfloat162float(hy));
        __nv_bfloat162 ph; ph.x = hx; ph.y = hy;
        __nv_bfloat162 pl; pl.x = lx; pl.y = ly;
        ((__nv_bfloat162*)g_x2hi)[(size_t)i * 256 + t] = ph;
        ((__nv_bfloat162*)g_x2lo)[(size_t)i * 256 + t] = pl;
    }
}

// ---------------- launch 4: GEMM2 bf16 (BM=64, grid 64) ----------------------
__global__ __launch_bounds__(256) void k_gemm2(
    const float* __restrict__ a2_src, const float* __restrict__ a2_dst)
{
    extern __shared__ float sm[];
    int b = blockIdx.x;
    gemm_bf16<64, Cc>(g_x2hi, g_x2lo, g_W2Thi, g_W2Tlo,
                      g_h2p, C2, b * 64, 0,
                      a2_src, a2_dst, g_s2i, g_s2j, sm);
}

// ------------- launch 5: layer-2 attention (grid Nn, proven R5 form) ---------
__global__ __launch_bounds__(64) void k_layer2(float* __restrict__ out) {
    __shared__ int   nbr_sh[MAXDEG];
    __shared__ float w_sh[MAXDEG];
    const unsigned FULL = 0xffffffffu;
    int i = blockIdx.x, t = threadIdx.x, lane = t & 31;
    int deg = g_deg[i];
    for (int jj = t; jj < deg; jj += 64) nbr_sh[jj] = g_nbr[i * MAXDEG + jj];
    __syncthreads();
    if (t < 32) {
        float sii = g_s2i[i];
        float ev[4];
        float m = -1e30f;
        #pragma unroll
        for (int it = 0; it < 4; it++) {
            int jj = it * 32 + lane;
            float e = -1e30f;
            if (jj < deg) {
                float xx = sii + g_s2j[nbr_sh[jj]];
                e = (xx >= 0.f) ? xx : 0.2f * xx;
            }
            ev[it] = e;
            m = fmaxf(m, e);
        }
        #pragma unroll
        for (int o = 16; o; o >>= 1) m = fmaxf(m, __shfl_xor_sync(FULL, m, o));
        float s = 0.f;
        #pragma unroll
        for (int it = 0; it < 4; it++) {
            int jj = it * 32 + lane;
            float w = (jj < deg) ? __expf(ev[it] - m) : 0.f;
            ev[it] = w;
            s += w;
        }
        #pragma unroll
        for (int o = 16; o; o >>= 1) s += __shfl_xor_sync(FULL, s, o);
        float inv = 1.f / s;
        #pragma unroll
        for (int it = 0; it < 4; it++) {
            int jj = it * 32 + lane;
            if (jj < deg) w_sh[jj] = ev[it] * inv;
        }
    }
    __syncthreads();
    if (t < Cc) {
        float acc = 0.f;
        for (int jj = 0; jj < deg; jj++)
            acc += w_sh[jj] * g_h2p[(size_t)nbr_sh[jj] * C2 + t];
        out[(size_t)i * Cc + t] = acc;
    }
}

// ---------------- launch -----------------------------------------------------
// words: STW1 = 2*128*20 + 2*64*20 = 7680; 3 stages + 4*128
#define SMEM_G1 ((3 * 7680 + 4 * 128) * 4)     // 94208
// STW2 = 2*64*20 + 2*64*20 = 5120; 3 stages + 4*64
#define SMEM_G2 ((3 * 5120 + 4 * 64) * 4)      // 62464

extern "C" void kernel_launch(void* const* d_in, const int* in_sizes, int n_in,
                              void* d_out, int out_size) {
    const float*         x      = (const float*)d_in[0];
    const unsigned char* adj    = (const unsigned char*)d_in[1];
    const float*         W1     = (const float*)d_in[2];
    const float*         a1_src = (const float*)d_in[3];
    const float*         a1_dst = (const float*)d_in[4];
    const float*         W2     = (const float*)d_in[5];
    const float*         a2_src = (const float*)d_in[6];
    const float*         a2_dst = (const float*)d_in[7];
    float* out = (float*)d_out;

    static bool init = false;
    if (!init) {
        init = true;
        cudaFuncSetAttribute(k_gemm1, cudaFuncAttributeMaxDynamicSharedMemorySize, SMEM_G1);
        cudaFuncSetAttribute(k_gemm2, cudaFuncAttributeMaxDynamicSharedMemorySize, SMEM_G2);
    }

    k_prep<<<1608, 256>>>(adj, x, W1, W2);
    k_gemm1<<<dim3(Hh, Nn / 128), 256, SMEM_G1>>>(a1_src, a1_dst);
    k_layer1<<<Nn, 256>>>();
    k_gemm2<<<64, 256, SMEM_G2>>>(a2_src, a2_dst);
    k_layer2<<<Nn, 64>>>(out);
}